// round 13
// baseline (speedup 1.0000x reference)
#include <cuda_runtime.h>
#include <cuda_bf16.h>
#include <math.h>
#include <stdint.h>

#define NROWS 65536
#define IN_DIM 1024
#define H1D 512
#define H2D 256
#define LATD 64
#define NCODE 1024
#define COMMIT_BETA 0.25
#define TAU 2e-4f

// -------- scratch (device globals: allocation-free per harness rules) --------
__device__ float g_h1[(size_t)NROWS * H1D];   // h1 approx, then repair h1 (dense)
__device__ float g_h2[(size_t)NROWS * H2D];   // h2 approx, then repair h2 (dense)
__device__ float g_zq[(size_t)NROWS * LATD];  // decoder input (codebook gather)
__device__ float g_zg[(size_t)NROWS * LATD];  // repair exact z (dense)
__device__ int   g_rlist[NROWS];
__device__ int   g_rcnt;
__device__ float g_esq[NCODE];
__device__ double g_loss;
// bf16 split weights, transposed to [N, K]
__device__ __nv_bfloat16 g_e1h[H1D * IN_DIM], g_e1l[H1D * IN_DIM];
__device__ __nv_bfloat16 g_e2h[H2D * H1D],    g_e2l[H2D * H1D];
__device__ __nv_bfloat16 g_w1h[H2D * LATD],   g_w1l[H2D * LATD];
__device__ __nv_bfloat16 g_w2h[H1D * H2D],    g_w2l[H1D * H2D];
__device__ __nv_bfloat16 g_w3h[IN_DIM * H1D], g_w3l[IN_DIM * H1D];

__device__ __forceinline__ uint32_t smem_u32(const void* p) {
    uint32_t a;
    asm("{ .reg .u64 t; cvta.to.shared.u64 t, %1; cvt.u32.u64 %0, t; }"
        : "=r"(a) : "l"(p));
    return a;
}
__device__ __forceinline__ void ldsm_x4(uint32_t& r0, uint32_t& r1,
                                        uint32_t& r2, uint32_t& r3, uint32_t addr) {
    asm volatile("ldmatrix.sync.aligned.m8n8.x4.shared.b16 {%0,%1,%2,%3}, [%4];"
                 : "=r"(r0), "=r"(r1), "=r"(r2), "=r"(r3) : "r"(addr));
}
__device__ __forceinline__ void mma_bf16(float* c, const uint32_t* a, const uint32_t* b) {
    asm volatile("mma.sync.aligned.m16n8k16.row.col.f32.bf16.bf16.f32 "
        "{%0,%1,%2,%3},{%4,%5,%6,%7},{%8,%9},{%0,%1,%2,%3};"
        : "+f"(c[0]), "+f"(c[1]), "+f"(c[2]), "+f"(c[3])
        : "r"(a[0]), "r"(a[1]), "r"(a[2]), "r"(a[3]), "r"(b[0]), "r"(b[1]));
}

// ============================================================================
// Warp-MMA bf16 GEMM, 3-term split: C += Ah*Bh + Al*Bh + Ah*Bl (fp32 acc)
// A fp32 split in-kernel; W pre-split transposed [N,K] bf16.
// CTA 128x128, BK=32, 8 warps. ACT: 1=relu, 2=tanh. grid=(N/128, M/128).
// ============================================================================
#define ASTR 40

template<int ACT>
__global__ __launch_bounds__(256, 1)
void mma_gemm(const float* __restrict__ A,
              const __nv_bfloat16* __restrict__ Wh,
              const __nv_bfloat16* __restrict__ Wl,
              const float* __restrict__ bias, float* __restrict__ C,
              int K, int N)
{
    __shared__ __align__(16) __nv_bfloat16 sAh[128 * ASTR];
    __shared__ __align__(16) __nv_bfloat16 sAl[128 * ASTR];
    __shared__ __align__(16) __nv_bfloat16 sBh[128 * ASTR];
    __shared__ __align__(16) __nv_bfloat16 sBl[128 * ASTR];

    const int tid = threadIdx.x;
    const int lane = tid & 31, wid = tid >> 5;
    const int m0 = blockIdx.y * 128, n0 = blockIdx.x * 128;
    const int wm = (wid & 1) * 64, wn = (wid >> 1) * 32;

    const uint32_t aAh = smem_u32(sAh), aAl = smem_u32(sAl);
    const uint32_t aBh = smem_u32(sBh), aBl = smem_u32(sBl);

    float acc[4][4][4];
    #pragma unroll
    for (int i = 0; i < 4; i++)
        #pragma unroll
        for (int j = 0; j < 4; j++)
            #pragma unroll
            for (int q = 0; q < 4; q++) acc[i][j][q] = 0.f;

    const int arow = tid >> 1;
    const int aq = tid & 1;

    float4 ra[4];
    uint4 rbh[2], rbl[2];

    auto loadG = [&](int k0) {
        const float4* ap = reinterpret_cast<const float4*>(
            &A[(size_t)(m0 + arow) * K + k0 + aq * 16]);
        #pragma unroll
        for (int j = 0; j < 4; j++) ra[j] = ap[j];
        const uint4* bph = reinterpret_cast<const uint4*>(
            &Wh[(size_t)(n0 + arow) * K + k0]);
        const uint4* bpl = reinterpret_cast<const uint4*>(
            &Wl[(size_t)(n0 + arow) * K + k0]);
        #pragma unroll
        for (int j = 0; j < 2; j++) {
            rbh[j] = bph[aq * 2 + j];
            rbl[j] = bpl[aq * 2 + j];
        }
    };
    auto storeS = [&]() {
        #pragma unroll
        for (int j = 0; j < 4; j++) {
            float4 v = ra[j];
            __nv_bfloat16 h0 = __float2bfloat16_rn(v.x);
            __nv_bfloat16 h1 = __float2bfloat16_rn(v.y);
            __nv_bfloat16 h2 = __float2bfloat16_rn(v.z);
            __nv_bfloat16 h3 = __float2bfloat16_rn(v.w);
            __nv_bfloat16 l0 = __float2bfloat16_rn(v.x - __bfloat162float(h0));
            __nv_bfloat16 l1 = __float2bfloat16_rn(v.y - __bfloat162float(h1));
            __nv_bfloat16 l2 = __float2bfloat16_rn(v.z - __bfloat162float(h2));
            __nv_bfloat16 l3 = __float2bfloat16_rn(v.w - __bfloat162float(h3));
            uint32_t hp0 = (uint32_t)__bfloat16_as_ushort(h0) |
                           ((uint32_t)__bfloat16_as_ushort(h1) << 16);
            uint32_t hp1 = (uint32_t)__bfloat16_as_ushort(h2) |
                           ((uint32_t)__bfloat16_as_ushort(h3) << 16);
            uint32_t lp0 = (uint32_t)__bfloat16_as_ushort(l0) |
                           ((uint32_t)__bfloat16_as_ushort(l1) << 16);
            uint32_t lp1 = (uint32_t)__bfloat16_as_ushort(l2) |
                           ((uint32_t)__bfloat16_as_ushort(l3) << 16);
            uint32_t off = (uint32_t)(arow * 80 + aq * 32 + j * 8);
            asm volatile("st.shared.v2.b32 [%0], {%1,%2};"
                         :: "r"(aAh + off), "r"(hp0), "r"(hp1) : "memory");
            asm volatile("st.shared.v2.b32 [%0], {%1,%2};"
                         :: "r"(aAl + off), "r"(lp0), "r"(lp1) : "memory");
        }
        #pragma unroll
        for (int j = 0; j < 2; j++) {
            uint32_t off = (uint32_t)(arow * 80 + (aq * 2 + j) * 16);
            asm volatile("st.shared.v4.b32 [%0], {%1,%2,%3,%4};"
                         :: "r"(aBh + off), "r"(rbh[j].x), "r"(rbh[j].y),
                            "r"(rbh[j].z), "r"(rbh[j].w) : "memory");
            asm volatile("st.shared.v4.b32 [%0], {%1,%2,%3,%4};"
                         :: "r"(aBl + off), "r"(rbl[j].x), "r"(rbl[j].y),
                            "r"(rbl[j].z), "r"(rbl[j].w) : "memory");
        }
    };
    auto compute = [&]() {
        #pragma unroll
        for (int ks = 0; ks < 2; ks++) {
            uint32_t ah[4][4], al[4][4], bh[4][2], bl[4][2];
            const int arl = lane & 15;
            const uint32_t ab = (uint32_t)((lane >> 4) * 16 + ks * 32);
            #pragma unroll
            for (int mt = 0; mt < 4; mt++) {
                uint32_t off = (uint32_t)((wm + mt * 16 + arl) * 80) + ab;
                ldsm_x4(ah[mt][0], ah[mt][1], ah[mt][2], ah[mt][3], aAh + off);
                ldsm_x4(al[mt][0], al[mt][1], al[mt][2], al[mt][3], aAl + off);
            }
            const int bn = (lane & 7) + ((lane >> 4) << 3);
            const uint32_t bb = (uint32_t)(((lane >> 3) & 1) * 16 + ks * 32);
            #pragma unroll
            for (int np = 0; np < 2; np++) {
                uint32_t off = (uint32_t)((wn + np * 16 + bn) * 80) + bb;
                uint32_t r0, r1, r2, r3;
                ldsm_x4(r0, r1, r2, r3, aBh + off);
                bh[np*2][0] = r0; bh[np*2][1] = r1;
                bh[np*2+1][0] = r2; bh[np*2+1][1] = r3;
                ldsm_x4(r0, r1, r2, r3, aBl + off);
                bl[np*2][0] = r0; bl[np*2][1] = r1;
                bl[np*2+1][0] = r2; bl[np*2+1][1] = r3;
            }
            #pragma unroll
            for (int mt = 0; mt < 4; mt++)
                #pragma unroll
                for (int nt = 0; nt < 4; nt++) {
                    mma_bf16(acc[mt][nt], ah[mt], bh[nt]);
                    mma_bf16(acc[mt][nt], al[mt], bh[nt]);
                    mma_bf16(acc[mt][nt], ah[mt], bl[nt]);
                }
        }
    };

    const int ntc = K >> 5;
    loadG(0);
    storeS();
    __syncthreads();
    #pragma unroll 1
    for (int ch = 1; ch < ntc; ch++) {
        loadG(ch * 32);
        compute();
        __syncthreads();
        storeS();
        __syncthreads();
    }
    compute();

    #pragma unroll
    for (int nt = 0; nt < 4; nt++) {
        const int col = n0 + wn + nt * 8 + (lane & 3) * 2;
        const float2 bv = *reinterpret_cast<const float2*>(&bias[col]);
        #pragma unroll
        for (int mt = 0; mt < 4; mt++) {
            const int r0 = m0 + wm + mt * 16 + (lane >> 2);
            float u0 = acc[mt][nt][0] + bv.x;
            float u1 = acc[mt][nt][1] + bv.y;
            float u2 = acc[mt][nt][2] + bv.x;
            float u3 = acc[mt][nt][3] + bv.y;
            if (ACT == 1) {
                u0 = fmaxf(u0, 0.f); u1 = fmaxf(u1, 0.f);
                u2 = fmaxf(u2, 0.f); u3 = fmaxf(u3, 0.f);
            } else {
                u0 = tanhf(u0); u1 = tanhf(u1);
                u2 = tanhf(u2); u3 = tanhf(u3);
            }
            *reinterpret_cast<float2*>(&C[(size_t)r0 * N + col]) = make_float2(u0, u1);
            *reinterpret_cast<float2*>(&C[(size_t)(r0 + 8) * N + col]) = make_float2(u2, u3);
        }
    }
}

// ============================================================================
// weight split: W[K,N] f32 -> Wh/Wl [N,K] bf16 (transposed)
// ============================================================================
__global__ void wsplit_kernel(const float* __restrict__ W,
                              __nv_bfloat16* __restrict__ Wh,
                              __nv_bfloat16* __restrict__ Wl, int K, int N)
{
    int i = blockIdx.x * 256 + threadIdx.x;
    if (i >= K * N) return;
    int n = i / K, k = i - n * K;
    float w = W[(size_t)k * N + n];
    __nv_bfloat16 h = __float2bfloat16_rn(w);
    Wh[i] = h;
    Wl[i] = __float2bfloat16_rn(w - __bfloat162float(h));
}

// ============================================================================
// Scalar fp32 SGEMM, bitwise-exact sequential-k.
// MODE 0: normal. MODE 1: dense rows with count early-out (repair chain).
// MODE 2: A rows indirected through rlist (clamped), C dense, count early-out.
// ============================================================================
template<int BM,int BN,int BK,int TM,int TN,int ACT,int MODE>
__global__ __launch_bounds__((BM/TM)*(BN/TN), 2)
void gemm_bias_act(const float* __restrict__ A, const float* __restrict__ B,
                   const float* __restrict__ bias, float* __restrict__ C,
                   int M, int N, int K,
                   const int* __restrict__ rows, const int* __restrict__ cntp)
{
    constexpr int NT = (BM/TM)*(BN/TN);
    constexpr int LA = (BM*BK)/(NT*4);
    constexpr int LB = (BK*BN)/(NT*4);

    __shared__ __align__(16) float As[2][BK][BM];
    __shared__ __align__(16) float Bs[2][BK][BN];
    __shared__ int srow[BM];

    const int tid = threadIdx.x;
    const int m0 = blockIdx.y * BM;
    const int n0 = blockIdx.x * BN;
    const int tx = tid % (BN/TN);
    const int ty = tid / (BN/TN);

    if (MODE >= 1) {
        const int cn = *cntp;
        if (cn == 0 || m0 >= cn) return;
        if (MODE == 2) {
            if (tid < BM) {
                int r = m0 + tid;
                srow[tid] = rows[r < cn ? r : (cn - 1)];
            }
            __syncthreads();
        }
    }

    float acc[TM][TN];
    #pragma unroll
    for (int i = 0; i < TM; i++)
        #pragma unroll
        for (int j = 0; j < TN; j++) acc[i][j] = 0.f;

    float4 ra[LA], rb[LB];

    #pragma unroll
    for (int j = 0; j < LA; j++) {
        int i = (tid + j*NT) * 4;
        int r = i / BK, c = i % BK;
        const int arow = (MODE == 2) ? srow[r] : (m0 + r);
        ra[j] = *reinterpret_cast<const float4*>(&A[(size_t)arow*K + c]);
    }
    #pragma unroll
    for (int j = 0; j < LB; j++) {
        int i = (tid + j*NT) * 4;
        int r = i / BN, c = i % BN;
        rb[j] = *reinterpret_cast<const float4*>(&B[(size_t)r*N + n0 + c]);
    }
    #pragma unroll
    for (int j = 0; j < LA; j++) {
        int i = (tid + j*NT) * 4;
        int r = i / BK, c = i % BK;
        As[0][c+0][r] = ra[j].x; As[0][c+1][r] = ra[j].y;
        As[0][c+2][r] = ra[j].z; As[0][c+3][r] = ra[j].w;
    }
    #pragma unroll
    for (int j = 0; j < LB; j++) {
        int i = (tid + j*NT) * 4;
        int r = i / BN, c = i % BN;
        *reinterpret_cast<float4*>(&Bs[0][r][c]) = rb[j];
    }
    __syncthreads();

    const int ntiles = K / BK;
    #pragma unroll 1
    for (int t = 1; t < ntiles; t++) {
        const int k0 = t * BK;
        #pragma unroll
        for (int j = 0; j < LA; j++) {
            int i = (tid + j*NT) * 4;
            int r = i / BK, c = i % BK;
            const int arow = (MODE == 2) ? srow[r] : (m0 + r);
            ra[j] = *reinterpret_cast<const float4*>(&A[(size_t)arow*K + k0 + c]);
        }
        #pragma unroll
        for (int j = 0; j < LB; j++) {
            int i = (tid + j*NT) * 4;
            int r = i / BN, c = i % BN;
            rb[j] = *reinterpret_cast<const float4*>(&B[(size_t)(k0 + r)*N + n0 + c]);
        }
        const int cur = (t - 1) & 1;
        #pragma unroll
        for (int k = 0; k < BK; k++) {
            float a[TM], b[TN];
            #pragma unroll
            for (int i = 0; i < TM; i += 4) {
                float4 v = *reinterpret_cast<const float4*>(&As[cur][k][ty*TM + i]);
                a[i] = v.x; a[i+1] = v.y; a[i+2] = v.z; a[i+3] = v.w;
            }
            #pragma unroll
            for (int j = 0; j < TN; j += 4) {
                float4 v = *reinterpret_cast<const float4*>(&Bs[cur][k][tx*TN + j]);
                b[j] = v.x; b[j+1] = v.y; b[j+2] = v.z; b[j+3] = v.w;
            }
            #pragma unroll
            for (int i = 0; i < TM; i++)
                #pragma unroll
                for (int j = 0; j < TN; j++)
                    acc[i][j] = fmaf(a[i], b[j], acc[i][j]);
        }
        const int nxt = t & 1;
        #pragma unroll
        for (int j = 0; j < LA; j++) {
            int i = (tid + j*NT) * 4;
            int r = i / BK, c = i % BK;
            As[nxt][c+0][r] = ra[j].x; As[nxt][c+1][r] = ra[j].y;
            As[nxt][c+2][r] = ra[j].z; As[nxt][c+3][r] = ra[j].w;
        }
        #pragma unroll
        for (int j = 0; j < LB; j++) {
            int i = (tid + j*NT) * 4;
            int r = i / BN, c = i % BN;
            *reinterpret_cast<float4*>(&Bs[nxt][r][c]) = rb[j];
        }
        __syncthreads();
    }
    {
        const int cur = (ntiles - 1) & 1;
        #pragma unroll
        for (int k = 0; k < BK; k++) {
            float a[TM], b[TN];
            #pragma unroll
            for (int i = 0; i < TM; i += 4) {
                float4 v = *reinterpret_cast<const float4*>(&As[cur][k][ty*TM + i]);
                a[i] = v.x; a[i+1] = v.y; a[i+2] = v.z; a[i+3] = v.w;
            }
            #pragma unroll
            for (int j = 0; j < TN; j += 4) {
                float4 v = *reinterpret_cast<const float4*>(&Bs[cur][k][tx*TN + j]);
                b[j] = v.x; b[j+1] = v.y; b[j+2] = v.z; b[j+3] = v.w;
            }
            #pragma unroll
            for (int i = 0; i < TM; i++)
                #pragma unroll
                for (int j = 0; j < TN; j++)
                    acc[i][j] = fmaf(a[i], b[j], acc[i][j]);
        }
    }

    float bv[TN];
    #pragma unroll
    for (int j = 0; j < TN; j++) bv[j] = bias[n0 + tx*TN + j];
    #pragma unroll
    for (int i = 0; i < TM; i++) {
        const int row = m0 + ty*TM + i;
        float* Cp = &C[(size_t)row*N + n0 + tx*TN];
        #pragma unroll
        for (int j = 0; j < TN; j += 4) {
            float vv[4];
            #pragma unroll
            for (int q = 0; q < 4; q++) {
                float u = acc[i][j+q] + bv[j+q];
                if (ACT == 1) u = fmaxf(u, 0.f);
                else if (ACT == 2) u = tanhf(u);
                vv[q] = u;
            }
            *reinterpret_cast<float4*>(&Cp[j]) = make_float4(vv[0], vv[1], vv[2], vv[3]);
        }
    }
}

// ============================================================================
// prep: codebook squared norms + zero loss + zero repair count
// ============================================================================
__global__ void prep_kernel(const float* __restrict__ cb)
{
    const int c = blockIdx.x * blockDim.x + threadIdx.x;
    if (c == 0) { g_loss = 0.0; g_rcnt = 0; }
    if (c < NCODE) {
        const float* p = &cb[(size_t)c * LATD];
        float s = 0.f;
        #pragma unroll
        for (int i = 0; i < LATD; i++) s = fmaf(p[i], p[i], s);
        g_esq[c] = s;
    }
}

// ============================================================================
// Approx VQ: reference-rounding dist formula on approx z. Tracks top-2;
// ambiguous rows (gap < TAU) appended to repair list. Writes idx, zq, loss.
// ============================================================================
__global__ __launch_bounds__(256)
void vq_approx_kernel(const float* __restrict__ z, const float* __restrict__ cb,
                      float* __restrict__ zq, float* __restrict__ idx_out)
{
    __shared__ __align__(16) float4 sc[128 * 16];
    __shared__ float sesq[128];
    __shared__ float wsum[8];

    const int tid = threadIdx.x;
    const int row = blockIdx.x * 256 + tid;

    float4 zr[16];
    const float4* zp = reinterpret_cast<const float4*>(&z[(size_t)row * LATD]);
    #pragma unroll
    for (int i = 0; i < 16; i++) zr[i] = zp[i];

    float z_sq = 0.f;
    #pragma unroll
    for (int i = 0; i < 16; i++) {
        z_sq = fmaf(zr[i].x, zr[i].x, z_sq);
        z_sq = fmaf(zr[i].y, zr[i].y, z_sq);
        z_sq = fmaf(zr[i].z, zr[i].z, z_sq);
        z_sq = fmaf(zr[i].w, zr[i].w, z_sq);
    }

    float best = 3.4028235e38f, second = 3.4028235e38f;
    int bi = 0;
    for (int c0 = 0; c0 < NCODE; c0 += 128) {
        __syncthreads();
        const float4* cp = reinterpret_cast<const float4*>(&cb[(size_t)c0 * LATD]);
        #pragma unroll
        for (int j = 0; j < 8; j++) sc[tid + j*256] = cp[tid + j*256];
        if (tid < 128) sesq[tid] = g_esq[c0 + tid];
        __syncthreads();

        #pragma unroll 4
        for (int c = 0; c < 128; c++) {
            const float4* e = &sc[c * 16];
            float acc = 0.f;
            #pragma unroll
            for (int i = 0; i < 16; i++) {
                float4 v = e[i];
                acc = fmaf(zr[i].x, v.x, acc);
                acc = fmaf(zr[i].y, v.y, acc);
                acc = fmaf(zr[i].z, v.z, acc);
                acc = fmaf(zr[i].w, v.w, acc);
            }
            float t = z_sq - 2.0f * acc;
            float d = t + sesq[c];
            if (d < best) { second = best; best = d; bi = c0 + c; }
            else if (d < second) { second = d; }
        }
    }

    // ambiguous -> repair list
    if (second - best < TAU) {
        int p = atomicAdd(&g_rcnt, 1);
        g_rlist[p] = row;
    }

    const float4* ep = reinterpret_cast<const float4*>(&cb[(size_t)bi * LATD]);
    float4* qp = reinterpret_cast<float4*>(&zq[(size_t)row * LATD]);
    float ls = 0.f;
    #pragma unroll
    for (int i = 0; i < 16; i++) {
        float4 e = ep[i];
        qp[i] = e;
        float dx = e.x - zr[i].x, dy = e.y - zr[i].y;
        float dz = e.z - zr[i].z, dw = e.w - zr[i].w;
        ls += dx*dx + dy*dy + dz*dz + dw*dw;
    }
    idx_out[row] = (float)bi;

    #pragma unroll
    for (int o = 16; o > 0; o >>= 1) ls += __shfl_down_sync(0xffffffffu, ls, o);
    if ((tid & 31) == 0) wsum[tid >> 5] = ls;
    __syncthreads();
    if (tid == 0) {
        float s = 0.f;
        #pragma unroll
        for (int i = 0; i < 8; i++) s += wsum[i];
        atomicAdd(&g_loss, (double)s);
    }
}

// ============================================================================
// Repair VQ: exact argmin on exact z (dense zg rows), scatter idx + zq.
// Bitwise identical dist formula/order as the reference.
// ============================================================================
__global__ __launch_bounds__(256)
void vq_repair_kernel(const float* __restrict__ zg, const float* __restrict__ cb,
                      float* __restrict__ zq, float* __restrict__ idx_out)
{
    __shared__ __align__(16) float4 sc[128 * 16];
    __shared__ float sesq[128];

    const int cn = g_rcnt;
    const int m0 = blockIdx.x * 256;
    if (cn == 0 || m0 >= cn) return;

    const int tid = threadIdx.x;
    int r = m0 + tid;
    if (r >= cn) r = cn - 1;

    float4 zr[16];
    const float4* zp = reinterpret_cast<const float4*>(&zg[(size_t)r * LATD]);
    #pragma unroll
    for (int i = 0; i < 16; i++) zr[i] = zp[i];

    float z_sq = 0.f;
    #pragma unroll
    for (int i = 0; i < 16; i++) {
        z_sq = fmaf(zr[i].x, zr[i].x, z_sq);
        z_sq = fmaf(zr[i].y, zr[i].y, z_sq);
        z_sq = fmaf(zr[i].z, zr[i].z, z_sq);
        z_sq = fmaf(zr[i].w, zr[i].w, z_sq);
    }

    float best = 3.4028235e38f;
    int bi = 0;
    for (int c0 = 0; c0 < NCODE; c0 += 128) {
        __syncthreads();
        const float4* cp = reinterpret_cast<const float4*>(&cb[(size_t)c0 * LATD]);
        #pragma unroll
        for (int j = 0; j < 8; j++) sc[tid + j*256] = cp[tid + j*256];
        if (tid < 128) sesq[tid] = g_esq[c0 + tid];
        __syncthreads();

        #pragma unroll 4
        for (int c = 0; c < 128; c++) {
            const float4* e = &sc[c * 16];
            float acc = 0.f;
            #pragma unroll
            for (int i = 0; i < 16; i++) {
                float4 v = e[i];
                acc = fmaf(zr[i].x, v.x, acc);
                acc = fmaf(zr[i].y, v.y, acc);
                acc = fmaf(zr[i].z, v.z, acc);
                acc = fmaf(zr[i].w, v.w, acc);
            }
            float t = z_sq - 2.0f * acc;
            float d = t + sesq[c];
            if (d < best) { best = d; bi = c0 + c; }
        }
    }

    const int orow = g_rlist[r];
    idx_out[orow] = (float)bi;
    const float4* ep = reinterpret_cast<const float4*>(&cb[(size_t)bi * LATD]);
    float4* qp = reinterpret_cast<float4*>(&zq[(size_t)orow * LATD]);
    #pragma unroll
    for (int i = 0; i < 16; i++) qp[i] = ep[i];
}

__global__ void fin_kernel(float* __restrict__ loss_out)
{
    loss_out[0] = (float)(COMMIT_BETA * g_loss / ((double)NROWS * LATD));
}

// ============================================================================
// launch
// ============================================================================
extern "C" void kernel_launch(void* const* d_in, const int* in_sizes, int n_in,
                              void* d_out, int out_size)
{
    const float* x   = (const float*)d_in[0];
    const float* We1 = (const float*)d_in[1];
    const float* be1 = (const float*)d_in[2];
    const float* We2 = (const float*)d_in[3];
    const float* be2 = (const float*)d_in[4];
    const float* We3 = (const float*)d_in[5];
    const float* be3 = (const float*)d_in[6];
    const float* cb  = (const float*)d_in[7];
    const float* Wd1 = (const float*)d_in[8];
    const float* bd1 = (const float*)d_in[9];
    const float* Wd2 = (const float*)d_in[10];
    const float* bd2 = (const float*)d_in[11];
    const float* Wd3 = (const float*)d_in[12];
    const float* bd3 = (const float*)d_in[13];

    float* out   = (float*)d_out;
    float* xrec  = out;
    float* zout  = out + (size_t)NROWS * IN_DIM;
    float* idxo  = zout + (size_t)NROWS * LATD;
    float* losso = idxo + NROWS;

    float *h1, *h2, *zq, *zg;
    int *rlist, *rcnt;
    cudaGetSymbolAddress((void**)&h1, g_h1);
    cudaGetSymbolAddress((void**)&h2, g_h2);
    cudaGetSymbolAddress((void**)&zq, g_zq);
    cudaGetSymbolAddress((void**)&zg, g_zg);
    cudaGetSymbolAddress((void**)&rlist, g_rlist);
    cudaGetSymbolAddress((void**)&rcnt, g_rcnt);
    __nv_bfloat16 *e1h, *e1l, *e2h, *e2l;
    __nv_bfloat16 *w1h, *w1l, *w2h, *w2l, *w3h, *w3l;
    cudaGetSymbolAddress((void**)&e1h, g_e1h);
    cudaGetSymbolAddress((void**)&e1l, g_e1l);
    cudaGetSymbolAddress((void**)&e2h, g_e2h);
    cudaGetSymbolAddress((void**)&e2l, g_e2l);
    cudaGetSymbolAddress((void**)&w1h, g_w1h);
    cudaGetSymbolAddress((void**)&w1l, g_w1l);
    cudaGetSymbolAddress((void**)&w2h, g_w2h);
    cudaGetSymbolAddress((void**)&w2l, g_w2l);
    cudaGetSymbolAddress((void**)&w3h, g_w3h);
    cudaGetSymbolAddress((void**)&w3l, g_w3l);

    prep_kernel<<<4, 256>>>(cb);
    wsplit_kernel<<<(IN_DIM*H1D + 255)/256, 256>>>(We1, e1h, e1l, IN_DIM, H1D);
    wsplit_kernel<<<(H1D*H2D  + 255)/256, 256>>>(We2, e2h, e2l, H1D, H2D);
    wsplit_kernel<<<(LATD*H2D + 255)/256, 256>>>(Wd1, w1h, w1l, LATD, H2D);
    wsplit_kernel<<<(H2D*H1D  + 255)/256, 256>>>(Wd2, w2h, w2l, H2D, H1D);
    wsplit_kernel<<<(H1D*IN_DIM+255)/256, 256>>>(Wd3, w3h, w3l, H1D, IN_DIM);

    // ---- approx encoder (tensor cores, 3-term split); e3 scalar (N=64) ----
    mma_gemm<1><<<dim3(H1D/128, NROWS/128), 256>>>(x,  e1h, e1l, be1, h1, IN_DIM, H1D);
    mma_gemm<1><<<dim3(H2D/128, NROWS/128), 256>>>(h1, e2h, e2l, be2, h2, H1D,  H2D);
    gemm_bias_act<128,64,16,8,4,0,0><<<dim3(1, NROWS/128), 256>>>(
        h2, We3, be3, zout, NROWS, LATD, H2D, nullptr, nullptr);

    // ---- approx VQ + ambiguity detection ----
    vq_approx_kernel<<<NROWS/256, 256>>>(zout, cb, zq, idxo);

    // ---- exact repair chain (bitwise fp32, only listed rows do real work) ----
    gemm_bias_act<128,128,16,8,8,1,2><<<dim3(H1D/128, NROWS/128), 256>>>(
        x,  We1, be1, h1, NROWS, H1D, IN_DIM, rlist, rcnt);
    gemm_bias_act<128,128,16,8,8,1,1><<<dim3(H2D/128, NROWS/128), 256>>>(
        h1, We2, be2, h2, NROWS, H2D, H1D, nullptr, rcnt);
    gemm_bias_act<128,64,16,8,4,0,1><<<dim3(1, NROWS/128), 256>>>(
        h2, We3, be3, zg, NROWS, LATD, H2D, nullptr, rcnt);
    vq_repair_kernel<<<NROWS/256, 256>>>(zg, cb, zq, idxo);

    // ---- decoder (tensor cores, 3-term split) ----
    mma_gemm<1><<<dim3(H2D/128,   NROWS/128), 256>>>(zq, w1h, w1l, bd1, h2,   LATD, H2D);
    mma_gemm<1><<<dim3(H1D/128,   NROWS/128), 256>>>(h2, w2h, w2l, bd2, h1,   H2D,  H1D);
    mma_gemm<2><<<dim3(IN_DIM/128,NROWS/128), 256>>>(h1, w3h, w3l, bd3, xrec, H1D,  IN_DIM);

    fin_kernel<<<1, 1>>>(losso);
}

// round 14
// speedup vs baseline: 1.0093x; 1.0093x over previous
#include <cuda_runtime.h>
#include <cuda_bf16.h>
#include <math.h>
#include <stdint.h>

#define NROWS 65536
#define IN_DIM 1024
#define H1D 512
#define H2D 256
#define LATD 64
#define NCODE 1024
#define COMMIT_BETA 0.25
#define TAU 2e-4f

// -------- scratch (device globals: allocation-free per harness rules) --------
__device__ float g_h1[(size_t)NROWS * H1D];   // h1 approx, then repair h1 (dense)
__device__ float g_h2[(size_t)NROWS * H2D];   // h2 approx, then repair h2 (dense)
__device__ float g_zq[(size_t)NROWS * LATD];  // decoder input (codebook gather)
__device__ float g_zg[(size_t)NROWS * LATD];  // repair exact z (dense)
__device__ int   g_rlist[NROWS];
__device__ int   g_rcnt;
__device__ float g_esq[NCODE];
__device__ double g_loss;
// bf16 split weights, transposed to [N, K]
__device__ __nv_bfloat16 g_e1h[H1D * IN_DIM], g_e1l[H1D * IN_DIM];
__device__ __nv_bfloat16 g_e2h[H2D * H1D],    g_e2l[H2D * H1D];
__device__ __nv_bfloat16 g_w1h[H2D * LATD],   g_w1l[H2D * LATD];
__device__ __nv_bfloat16 g_w2h[H1D * H2D],    g_w2l[H1D * H2D];
__device__ __nv_bfloat16 g_w3h[IN_DIM * H1D], g_w3l[IN_DIM * H1D];

__device__ __forceinline__ uint32_t smem_u32(const void* p) {
    uint32_t a;
    asm("{ .reg .u64 t; cvta.to.shared.u64 t, %1; cvt.u32.u64 %0, t; }"
        : "=r"(a) : "l"(p));
    return a;
}
__device__ __forceinline__ void ldsm_x4(uint32_t& r0, uint32_t& r1,
                                        uint32_t& r2, uint32_t& r3, uint32_t addr) {
    asm volatile("ldmatrix.sync.aligned.m8n8.x4.shared.b16 {%0,%1,%2,%3}, [%4];"
                 : "=r"(r0), "=r"(r1), "=r"(r2), "=r"(r3) : "r"(addr));
}
__device__ __forceinline__ void mma_bf16(float* c, const uint32_t* a, const uint32_t* b) {
    asm volatile("mma.sync.aligned.m16n8k16.row.col.f32.bf16.bf16.f32 "
        "{%0,%1,%2,%3},{%4,%5,%6,%7},{%8,%9},{%0,%1,%2,%3};"
        : "+f"(c[0]), "+f"(c[1]), "+f"(c[2]), "+f"(c[3])
        : "r"(a[0]), "r"(a[1]), "r"(a[2]), "r"(a[3]), "r"(b[0]), "r"(b[1]));
}

// ============================================================================
// Warp-MMA bf16 GEMM, 3-term split: C += Ah*Bh + Al*Bh + Ah*Bl (fp32 acc).
// DOUBLE-BUFFERED dynamic smem: one __syncthreads per K-chunk; storeS(next)
// overlaps other warps' compute(cur). CTA 128x128, BK=32, 8 warps.
// ACT: 1=relu, 2=tanh. grid=(N/128, M/128).
// ============================================================================
#define MMA_BUFB 40960u          // per-buffer bytes (4 arrays x 10240)
#define MMA_DSM  (2 * 40960)     // dynamic smem total

template<int ACT>
__global__ __launch_bounds__(256, 1)
void mma_gemm(const float* __restrict__ A,
              const __nv_bfloat16* __restrict__ Wh,
              const __nv_bfloat16* __restrict__ Wl,
              const float* __restrict__ bias, float* __restrict__ C,
              int K, int N)
{
    extern __shared__ char dsm[];
    const uint32_t sb = smem_u32(dsm);

    const int tid = threadIdx.x;
    const int lane = tid & 31, wid = tid >> 5;
    const int m0 = blockIdx.y * 128, n0 = blockIdx.x * 128;
    const int wm = (wid & 1) * 64, wn = (wid >> 1) * 32;

    float acc[4][4][4];
    #pragma unroll
    for (int i = 0; i < 4; i++)
        #pragma unroll
        for (int j = 0; j < 4; j++)
            #pragma unroll
            for (int q = 0; q < 4; q++) acc[i][j][q] = 0.f;

    const int arow = tid >> 1;
    const int aq = tid & 1;

    float4 ra[4];
    uint4 rbh[2], rbl[2];

    auto loadG = [&](int k0) {
        const float4* ap = reinterpret_cast<const float4*>(
            &A[(size_t)(m0 + arow) * K + k0 + aq * 16]);
        #pragma unroll
        for (int j = 0; j < 4; j++) ra[j] = ap[j];
        const uint4* bph = reinterpret_cast<const uint4*>(
            &Wh[(size_t)(n0 + arow) * K + k0]);
        const uint4* bpl = reinterpret_cast<const uint4*>(
            &Wl[(size_t)(n0 + arow) * K + k0]);
        #pragma unroll
        for (int j = 0; j < 2; j++) {
            rbh[j] = bph[aq * 2 + j];
            rbl[j] = bpl[aq * 2 + j];
        }
    };
    auto storeS = [&](int p) {
        const uint32_t b = sb + (uint32_t)p * MMA_BUFB;
        const uint32_t aAh = b, aAl = b + 10240u;
        const uint32_t aBh = b + 20480u, aBl = b + 30720u;
        #pragma unroll
        for (int j = 0; j < 4; j++) {
            float4 v = ra[j];
            __nv_bfloat16 h0 = __float2bfloat16_rn(v.x);
            __nv_bfloat16 h1 = __float2bfloat16_rn(v.y);
            __nv_bfloat16 h2 = __float2bfloat16_rn(v.z);
            __nv_bfloat16 h3 = __float2bfloat16_rn(v.w);
            __nv_bfloat16 l0 = __float2bfloat16_rn(v.x - __bfloat162float(h0));
            __nv_bfloat16 l1 = __float2bfloat16_rn(v.y - __bfloat162float(h1));
            __nv_bfloat16 l2 = __float2bfloat16_rn(v.z - __bfloat162float(h2));
            __nv_bfloat16 l3 = __float2bfloat16_rn(v.w - __bfloat162float(h3));
            uint32_t hp0 = (uint32_t)__bfloat16_as_ushort(h0) |
                           ((uint32_t)__bfloat16_as_ushort(h1) << 16);
            uint32_t hp1 = (uint32_t)__bfloat16_as_ushort(h2) |
                           ((uint32_t)__bfloat16_as_ushort(h3) << 16);
            uint32_t lp0 = (uint32_t)__bfloat16_as_ushort(l0) |
                           ((uint32_t)__bfloat16_as_ushort(l1) << 16);
            uint32_t lp1 = (uint32_t)__bfloat16_as_ushort(l2) |
                           ((uint32_t)__bfloat16_as_ushort(l3) << 16);
            uint32_t off = (uint32_t)(arow * 80 + aq * 32 + j * 8);
            asm volatile("st.shared.v2.b32 [%0], {%1,%2};"
                         :: "r"(aAh + off), "r"(hp0), "r"(hp1) : "memory");
            asm volatile("st.shared.v2.b32 [%0], {%1,%2};"
                         :: "r"(aAl + off), "r"(lp0), "r"(lp1) : "memory");
        }
        #pragma unroll
        for (int j = 0; j < 2; j++) {
            uint32_t off = (uint32_t)(arow * 80 + (aq * 2 + j) * 16);
            asm volatile("st.shared.v4.b32 [%0], {%1,%2,%3,%4};"
                         :: "r"(aBh + off), "r"(rbh[j].x), "r"(rbh[j].y),
                            "r"(rbh[j].z), "r"(rbh[j].w) : "memory");
            asm volatile("st.shared.v4.b32 [%0], {%1,%2,%3,%4};"
                         :: "r"(aBl + off), "r"(rbl[j].x), "r"(rbl[j].y),
                            "r"(rbl[j].z), "r"(rbl[j].w) : "memory");
        }
    };
    auto compute = [&](int p) {
        const uint32_t b = sb + (uint32_t)p * MMA_BUFB;
        const uint32_t aAh = b, aAl = b + 10240u;
        const uint32_t aBh = b + 20480u, aBl = b + 30720u;
        #pragma unroll
        for (int ks = 0; ks < 2; ks++) {
            uint32_t ah[4][4], al[4][4], bh[4][2], bl[4][2];
            const int arl = lane & 15;
            const uint32_t ab = (uint32_t)((lane >> 4) * 16 + ks * 32);
            #pragma unroll
            for (int mt = 0; mt < 4; mt++) {
                uint32_t off = (uint32_t)((wm + mt * 16 + arl) * 80) + ab;
                ldsm_x4(ah[mt][0], ah[mt][1], ah[mt][2], ah[mt][3], aAh + off);
                ldsm_x4(al[mt][0], al[mt][1], al[mt][2], al[mt][3], aAl + off);
            }
            const int bn = (lane & 7) + ((lane >> 4) << 3);
            const uint32_t bb = (uint32_t)(((lane >> 3) & 1) * 16 + ks * 32);
            #pragma unroll
            for (int np = 0; np < 2; np++) {
                uint32_t off = (uint32_t)((wn + np * 16 + bn) * 80) + bb;
                uint32_t r0, r1, r2, r3;
                ldsm_x4(r0, r1, r2, r3, aBh + off);
                bh[np*2][0] = r0; bh[np*2][1] = r1;
                bh[np*2+1][0] = r2; bh[np*2+1][1] = r3;
                ldsm_x4(r0, r1, r2, r3, aBl + off);
                bl[np*2][0] = r0; bl[np*2][1] = r1;
                bl[np*2+1][0] = r2; bl[np*2+1][1] = r3;
            }
            #pragma unroll
            for (int mt = 0; mt < 4; mt++)
                #pragma unroll
                for (int nt = 0; nt < 4; nt++) {
                    mma_bf16(acc[mt][nt], ah[mt], bh[nt]);
                    mma_bf16(acc[mt][nt], al[mt], bh[nt]);
                    mma_bf16(acc[mt][nt], ah[mt], bl[nt]);
                }
        }
    };

    const int ntc = K >> 5;
    loadG(0);
    storeS(0);
    __syncthreads();
    #pragma unroll 1
    for (int ch = 0; ch < ntc - 1; ch++) {
        loadG((ch + 1) << 5);
        compute(ch & 1);          // read buffer ch&1
        storeS((ch + 1) & 1);     // fill other buffer (safe: prev sync fenced it)
        __syncthreads();
    }
    compute((ntc - 1) & 1);

    #pragma unroll
    for (int nt = 0; nt < 4; nt++) {
        const int col = n0 + wn + nt * 8 + (lane & 3) * 2;
        const float2 bv = *reinterpret_cast<const float2*>(&bias[col]);
        #pragma unroll
        for (int mt = 0; mt < 4; mt++) {
            const int r0 = m0 + wm + mt * 16 + (lane >> 2);
            float u0 = acc[mt][nt][0] + bv.x;
            float u1 = acc[mt][nt][1] + bv.y;
            float u2 = acc[mt][nt][2] + bv.x;
            float u3 = acc[mt][nt][3] + bv.y;
            if (ACT == 1) {
                u0 = fmaxf(u0, 0.f); u1 = fmaxf(u1, 0.f);
                u2 = fmaxf(u2, 0.f); u3 = fmaxf(u3, 0.f);
            } else {
                u0 = tanhf(u0); u1 = tanhf(u1);
                u2 = tanhf(u2); u3 = tanhf(u3);
            }
            *reinterpret_cast<float2*>(&C[(size_t)r0 * N + col]) = make_float2(u0, u1);
            *reinterpret_cast<float2*>(&C[(size_t)(r0 + 8) * N + col]) = make_float2(u2, u3);
        }
    }
}

// ============================================================================
// weight split: W[K,N] f32 -> Wh/Wl [N,K] bf16 (transposed)
// ============================================================================
__global__ void wsplit_kernel(const float* __restrict__ W,
                              __nv_bfloat16* __restrict__ Wh,
                              __nv_bfloat16* __restrict__ Wl, int K, int N)
{
    int i = blockIdx.x * 256 + threadIdx.x;
    if (i >= K * N) return;
    int n = i / K, k = i - n * K;
    float w = W[(size_t)k * N + n];
    __nv_bfloat16 h = __float2bfloat16_rn(w);
    Wh[i] = h;
    Wl[i] = __float2bfloat16_rn(w - __bfloat162float(h));
}

// ============================================================================
// Scalar fp32 SGEMM, bitwise-exact sequential-k.
// MODE 0: normal. MODE 1: dense rows with count early-out (repair chain).
// MODE 2: A rows indirected through rlist (clamped), C dense, count early-out.
// ============================================================================
template<int BM,int BN,int BK,int TM,int TN,int ACT,int MODE>
__global__ __launch_bounds__((BM/TM)*(BN/TN), 2)
void gemm_bias_act(const float* __restrict__ A, const float* __restrict__ B,
                   const float* __restrict__ bias, float* __restrict__ C,
                   int M, int N, int K,
                   const int* __restrict__ rows, const int* __restrict__ cntp)
{
    constexpr int NT = (BM/TM)*(BN/TN);
    constexpr int LA = (BM*BK)/(NT*4);
    constexpr int LB = (BK*BN)/(NT*4);

    __shared__ __align__(16) float As[2][BK][BM];
    __shared__ __align__(16) float Bs[2][BK][BN];
    __shared__ int srow[BM];

    const int tid = threadIdx.x;
    const int m0 = blockIdx.y * BM;
    const int n0 = blockIdx.x * BN;
    const int tx = tid % (BN/TN);
    const int ty = tid / (BN/TN);

    if (MODE >= 1) {
        const int cn = *cntp;
        if (cn == 0 || m0 >= cn) return;
        if (MODE == 2) {
            if (tid < BM) {
                int r = m0 + tid;
                srow[tid] = rows[r < cn ? r : (cn - 1)];
            }
            __syncthreads();
        }
    }

    float acc[TM][TN];
    #pragma unroll
    for (int i = 0; i < TM; i++)
        #pragma unroll
        for (int j = 0; j < TN; j++) acc[i][j] = 0.f;

    float4 ra[LA], rb[LB];

    #pragma unroll
    for (int j = 0; j < LA; j++) {
        int i = (tid + j*NT) * 4;
        int r = i / BK, c = i % BK;
        const int ar = (MODE == 2) ? srow[r] : (m0 + r);
        ra[j] = *reinterpret_cast<const float4*>(&A[(size_t)ar*K + c]);
    }
    #pragma unroll
    for (int j = 0; j < LB; j++) {
        int i = (tid + j*NT) * 4;
        int r = i / BN, c = i % BN;
        rb[j] = *reinterpret_cast<const float4*>(&B[(size_t)r*N + n0 + c]);
    }
    #pragma unroll
    for (int j = 0; j < LA; j++) {
        int i = (tid + j*NT) * 4;
        int r = i / BK, c = i % BK;
        As[0][c+0][r] = ra[j].x; As[0][c+1][r] = ra[j].y;
        As[0][c+2][r] = ra[j].z; As[0][c+3][r] = ra[j].w;
    }
    #pragma unroll
    for (int j = 0; j < LB; j++) {
        int i = (tid + j*NT) * 4;
        int r = i / BN, c = i % BN;
        *reinterpret_cast<float4*>(&Bs[0][r][c]) = rb[j];
    }
    __syncthreads();

    const int ntiles = K / BK;
    #pragma unroll 1
    for (int t = 1; t < ntiles; t++) {
        const int k0 = t * BK;
        #pragma unroll
        for (int j = 0; j < LA; j++) {
            int i = (tid + j*NT) * 4;
            int r = i / BK, c = i % BK;
            const int ar = (MODE == 2) ? srow[r] : (m0 + r);
            ra[j] = *reinterpret_cast<const float4*>(&A[(size_t)ar*K + k0 + c]);
        }
        #pragma unroll
        for (int j = 0; j < LB; j++) {
            int i = (tid + j*NT) * 4;
            int r = i / BN, c = i % BN;
            rb[j] = *reinterpret_cast<const float4*>(&B[(size_t)(k0 + r)*N + n0 + c]);
        }
        const int cur = (t - 1) & 1;
        #pragma unroll
        for (int k = 0; k < BK; k++) {
            float a[TM], b[TN];
            #pragma unroll
            for (int i = 0; i < TM; i += 4) {
                float4 v = *reinterpret_cast<const float4*>(&As[cur][k][ty*TM + i]);
                a[i] = v.x; a[i+1] = v.y; a[i+2] = v.z; a[i+3] = v.w;
            }
            #pragma unroll
            for (int j = 0; j < TN; j += 4) {
                float4 v = *reinterpret_cast<const float4*>(&Bs[cur][k][tx*TN + j]);
                b[j] = v.x; b[j+1] = v.y; b[j+2] = v.z; b[j+3] = v.w;
            }
            #pragma unroll
            for (int i = 0; i < TM; i++)
                #pragma unroll
                for (int j = 0; j < TN; j++)
                    acc[i][j] = fmaf(a[i], b[j], acc[i][j]);
        }
        const int nxt = t & 1;
        #pragma unroll
        for (int j = 0; j < LA; j++) {
            int i = (tid + j*NT) * 4;
            int r = i / BK, c = i % BK;
            As[nxt][c+0][r] = ra[j].x; As[nxt][c+1][r] = ra[j].y;
            As[nxt][c+2][r] = ra[j].z; As[nxt][c+3][r] = ra[j].w;
        }
        #pragma unroll
        for (int j = 0; j < LB; j++) {
            int i = (tid + j*NT) * 4;
            int r = i / BN, c = i % BN;
            *reinterpret_cast<float4*>(&Bs[nxt][r][c]) = rb[j];
        }
        __syncthreads();
    }
    {
        const int cur = (ntiles - 1) & 1;
        #pragma unroll
        for (int k = 0; k < BK; k++) {
            float a[TM], b[TN];
            #pragma unroll
            for (int i = 0; i < TM; i += 4) {
                float4 v = *reinterpret_cast<const float4*>(&As[cur][k][ty*TM + i]);
                a[i] = v.x; a[i+1] = v.y; a[i+2] = v.z; a[i+3] = v.w;
            }
            #pragma unroll
            for (int j = 0; j < TN; j += 4) {
                float4 v = *reinterpret_cast<const float4*>(&Bs[cur][k][tx*TN + j]);
                b[j] = v.x; b[j+1] = v.y; b[j+2] = v.z; b[j+3] = v.w;
            }
            #pragma unroll
            for (int i = 0; i < TM; i++)
                #pragma unroll
                for (int j = 0; j < TN; j++)
                    acc[i][j] = fmaf(a[i], b[j], acc[i][j]);
        }
    }

    float bv[TN];
    #pragma unroll
    for (int j = 0; j < TN; j++) bv[j] = bias[n0 + tx*TN + j];
    #pragma unroll
    for (int i = 0; i < TM; i++) {
        const int row = m0 + ty*TM + i;
        float* Cp = &C[(size_t)row*N + n0 + tx*TN];
        #pragma unroll
        for (int j = 0; j < TN; j += 4) {
            float vv[4];
            #pragma unroll
            for (int q = 0; q < 4; q++) {
                float u = acc[i][j+q] + bv[j+q];
                if (ACT == 1) u = fmaxf(u, 0.f);
                else if (ACT == 2) u = tanhf(u);
                vv[q] = u;
            }
            *reinterpret_cast<float4*>(&Cp[j]) = make_float4(vv[0], vv[1], vv[2], vv[3]);
        }
    }
}

// ============================================================================
// prep: codebook squared norms + zero loss + zero repair count
// ============================================================================
__global__ void prep_kernel(const float* __restrict__ cb)
{
    const int c = blockIdx.x * blockDim.x + threadIdx.x;
    if (c == 0) { g_loss = 0.0; g_rcnt = 0; }
    if (c < NCODE) {
        const float* p = &cb[(size_t)c * LATD];
        float s = 0.f;
        #pragma unroll
        for (int i = 0; i < LATD; i++) s = fmaf(p[i], p[i], s);
        g_esq[c] = s;
    }
}

// ============================================================================
// Approx VQ: reference-rounding dist formula on approx z. Tracks top-2;
// ambiguous rows (gap < TAU) appended to repair list. Writes idx, zq, loss.
// ============================================================================
__global__ __launch_bounds__(256)
void vq_approx_kernel(const float* __restrict__ z, const float* __restrict__ cb,
                      float* __restrict__ zq, float* __restrict__ idx_out)
{
    __shared__ __align__(16) float4 sc[128 * 16];
    __shared__ float sesq[128];
    __shared__ float wsum[8];

    const int tid = threadIdx.x;
    const int row = blockIdx.x * 256 + tid;

    float4 zr[16];
    const float4* zp = reinterpret_cast<const float4*>(&z[(size_t)row * LATD]);
    #pragma unroll
    for (int i = 0; i < 16; i++) zr[i] = zp[i];

    float z_sq = 0.f;
    #pragma unroll
    for (int i = 0; i < 16; i++) {
        z_sq = fmaf(zr[i].x, zr[i].x, z_sq);
        z_sq = fmaf(zr[i].y, zr[i].y, z_sq);
        z_sq = fmaf(zr[i].z, zr[i].z, z_sq);
        z_sq = fmaf(zr[i].w, zr[i].w, z_sq);
    }

    float best = 3.4028235e38f, second = 3.4028235e38f;
    int bi = 0;
    for (int c0 = 0; c0 < NCODE; c0 += 128) {
        __syncthreads();
        const float4* cp = reinterpret_cast<const float4*>(&cb[(size_t)c0 * LATD]);
        #pragma unroll
        for (int j = 0; j < 8; j++) sc[tid + j*256] = cp[tid + j*256];
        if (tid < 128) sesq[tid] = g_esq[c0 + tid];
        __syncthreads();

        #pragma unroll 4
        for (int c = 0; c < 128; c++) {
            const float4* e = &sc[c * 16];
            float acc = 0.f;
            #pragma unroll
            for (int i = 0; i < 16; i++) {
                float4 v = e[i];
                acc = fmaf(zr[i].x, v.x, acc);
                acc = fmaf(zr[i].y, v.y, acc);
                acc = fmaf(zr[i].z, v.z, acc);
                acc = fmaf(zr[i].w, v.w, acc);
            }
            float t = z_sq - 2.0f * acc;
            float d = t + sesq[c];
            if (d < best) { second = best; best = d; bi = c0 + c; }
            else if (d < second) { second = d; }
        }
    }

    if (second - best < TAU) {
        int p = atomicAdd(&g_rcnt, 1);
        g_rlist[p] = row;
    }

    const float4* ep = reinterpret_cast<const float4*>(&cb[(size_t)bi * LATD]);
    float4* qp = reinterpret_cast<float4*>(&zq[(size_t)row * LATD]);
    float ls = 0.f;
    #pragma unroll
    for (int i = 0; i < 16; i++) {
        float4 e = ep[i];
        qp[i] = e;
        float dx = e.x - zr[i].x, dy = e.y - zr[i].y;
        float dz = e.z - zr[i].z, dw = e.w - zr[i].w;
        ls += dx*dx + dy*dy + dz*dz + dw*dw;
    }
    idx_out[row] = (float)bi;

    #pragma unroll
    for (int o = 16; o > 0; o >>= 1) ls += __shfl_down_sync(0xffffffffu, ls, o);
    if ((tid & 31) == 0) wsum[tid >> 5] = ls;
    __syncthreads();
    if (tid == 0) {
        float s = 0.f;
        #pragma unroll
        for (int i = 0; i < 8; i++) s += wsum[i];
        atomicAdd(&g_loss, (double)s);
    }
}

// ============================================================================
// Repair VQ: exact argmin on exact z (dense zg rows), scatter idx + zq.
// ============================================================================
__global__ __launch_bounds__(256)
void vq_repair_kernel(const float* __restrict__ zg, const float* __restrict__ cb,
                      float* __restrict__ zq, float* __restrict__ idx_out)
{
    __shared__ __align__(16) float4 sc[128 * 16];
    __shared__ float sesq[128];

    const int cn = g_rcnt;
    const int m0 = blockIdx.x * 256;
    if (cn == 0 || m0 >= cn) return;

    const int tid = threadIdx.x;
    int r = m0 + tid;
    if (r >= cn) r = cn - 1;

    float4 zr[16];
    const float4* zp = reinterpret_cast<const float4*>(&zg[(size_t)r * LATD]);
    #pragma unroll
    for (int i = 0; i < 16; i++) zr[i] = zp[i];

    float z_sq = 0.f;
    #pragma unroll
    for (int i = 0; i < 16; i++) {
        z_sq = fmaf(zr[i].x, zr[i].x, z_sq);
        z_sq = fmaf(zr[i].y, zr[i].y, z_sq);
        z_sq = fmaf(zr[i].z, zr[i].z, z_sq);
        z_sq = fmaf(zr[i].w, zr[i].w, z_sq);
    }

    float best = 3.4028235e38f;
    int bi = 0;
    for (int c0 = 0; c0 < NCODE; c0 += 128) {
        __syncthreads();
        const float4* cp = reinterpret_cast<const float4*>(&cb[(size_t)c0 * LATD]);
        #pragma unroll
        for (int j = 0; j < 8; j++) sc[tid + j*256] = cp[tid + j*256];
        if (tid < 128) sesq[tid] = g_esq[c0 + tid];
        __syncthreads();

        #pragma unroll 4
        for (int c = 0; c < 128; c++) {
            const float4* e = &sc[c * 16];
            float acc = 0.f;
            #pragma unroll
            for (int i = 0; i < 16; i++) {
                float4 v = e[i];
                acc = fmaf(zr[i].x, v.x, acc);
                acc = fmaf(zr[i].y, v.y, acc);
                acc = fmaf(zr[i].z, v.z, acc);
                acc = fmaf(zr[i].w, v.w, acc);
            }
            float t = z_sq - 2.0f * acc;
            float d = t + sesq[c];
            if (d < best) { best = d; bi = c0 + c; }
        }
    }

    const int orow = g_rlist[r];
    idx_out[orow] = (float)bi;
    const float4* ep = reinterpret_cast<const float4*>(&cb[(size_t)bi * LATD]);
    float4* qp = reinterpret_cast<float4*>(&zq[(size_t)orow * LATD]);
    #pragma unroll
    for (int i = 0; i < 16; i++) qp[i] = ep[i];
}

__global__ void fin_kernel(float* __restrict__ loss_out)
{
    loss_out[0] = (float)(COMMIT_BETA * g_loss / ((double)NROWS * LATD));
}

// ============================================================================
// launch  (order arranged so ncu -s 5 -c 1 captures the e1 mma_gemm)
// ============================================================================
extern "C" void kernel_launch(void* const* d_in, const int* in_sizes, int n_in,
                              void* d_out, int out_size)
{
    const float* x   = (const float*)d_in[0];
    const float* We1 = (const float*)d_in[1];
    const float* be1 = (const float*)d_in[2];
    const float* We2 = (const float*)d_in[3];
    const float* be2 = (const float*)d_in[4];
    const float* We3 = (const float*)d_in[5];
    const float* be3 = (const float*)d_in[6];
    const float* cb  = (const float*)d_in[7];
    const float* Wd1 = (const float*)d_in[8];
    const float* bd1 = (const float*)d_in[9];
    const float* Wd2 = (const float*)d_in[10];
    const float* bd2 = (const float*)d_in[11];
    const float* Wd3 = (const float*)d_in[12];
    const float* bd3 = (const float*)d_in[13];

    float* out   = (float*)d_out;
    float* xrec  = out;
    float* zout  = out + (size_t)NROWS * IN_DIM;
    float* idxo  = zout + (size_t)NROWS * LATD;
    float* losso = idxo + NROWS;

    float *h1, *h2, *zq, *zg;
    int *rlist, *rcnt;
    cudaGetSymbolAddress((void**)&h1, g_h1);
    cudaGetSymbolAddress((void**)&h2, g_h2);
    cudaGetSymbolAddress((void**)&zq, g_zq);
    cudaGetSymbolAddress((void**)&zg, g_zg);
    cudaGetSymbolAddress((void**)&rlist, g_rlist);
    cudaGetSymbolAddress((void**)&rcnt, g_rcnt);
    __nv_bfloat16 *e1h, *e1l, *e2h, *e2l;
    __nv_bfloat16 *w1h, *w1l, *w2h, *w2l, *w3h, *w3l;
    cudaGetSymbolAddress((void**)&e1h, g_e1h);
    cudaGetSymbolAddress((void**)&e1l, g_e1l);
    cudaGetSymbolAddress((void**)&e2h, g_e2h);
    cudaGetSymbolAddress((void**)&e2l, g_e2l);
    cudaGetSymbolAddress((void**)&w1h, g_w1h);
    cudaGetSymbolAddress((void**)&w1l, g_w1l);
    cudaGetSymbolAddress((void**)&w2h, g_w2h);
    cudaGetSymbolAddress((void**)&w2l, g_w2l);
    cudaGetSymbolAddress((void**)&w3h, g_w3h);
    cudaGetSymbolAddress((void**)&w3l, g_w3l);

    cudaFuncSetAttribute(mma_gemm<1>, cudaFuncAttributeMaxDynamicSharedMemorySize, MMA_DSM);
    cudaFuncSetAttribute(mma_gemm<2>, cudaFuncAttributeMaxDynamicSharedMemorySize, MMA_DSM);

    // launches 0-4
    prep_kernel<<<4, 256>>>(cb);
    wsplit_kernel<<<(IN_DIM*H1D + 255)/256, 256>>>(We1, e1h, e1l, IN_DIM, H1D);
    wsplit_kernel<<<(H1D*H2D  + 255)/256, 256>>>(We2, e2h, e2l, H1D, H2D);
    wsplit_kernel<<<(LATD*H2D + 255)/256, 256>>>(Wd1, w1h, w1l, LATD, H2D);
    wsplit_kernel<<<(H2D*H1D  + 255)/256, 256>>>(Wd2, w2h, w2l, H2D, H1D);

    // launch 5: e1 (captured by ncu -s 5 -c 1)
    mma_gemm<1><<<dim3(H1D/128, NROWS/128), 256, MMA_DSM>>>(x,  e1h, e1l, be1, h1, IN_DIM, H1D);
    wsplit_kernel<<<(H1D*IN_DIM+255)/256, 256>>>(Wd3, w3h, w3l, H1D, IN_DIM);
    mma_gemm<1><<<dim3(H2D/128, NROWS/128), 256, MMA_DSM>>>(h1, e2h, e2l, be2, h2, H1D, H2D);
    gemm_bias_act<128,64,16,8,4,0,0><<<dim3(1, NROWS/128), 256>>>(
        h2, We3, be3, zout, NROWS, LATD, H2D, nullptr, nullptr);

    // approx VQ + ambiguity detection
    vq_approx_kernel<<<NROWS/256, 256>>>(zout, cb, zq, idxo);

    // exact repair chain (bitwise fp32, only listed rows do real work)
    gemm_bias_act<128,128,16,8,8,1,2><<<dim3(H1D/128, NROWS/128), 256>>>(
        x,  We1, be1, h1, NROWS, H1D, IN_DIM, rlist, rcnt);
    gemm_bias_act<128,128,16,8,8,1,1><<<dim3(H2D/128, NROWS/128), 256>>>(
        h1, We2, be2, h2, NROWS, H2D, H1D, nullptr, rcnt);
    gemm_bias_act<128,64,16,8,4,0,1><<<dim3(1, NROWS/128), 256>>>(
        h2, We3, be3, zg, NROWS, LATD, H2D, nullptr, rcnt);
    vq_repair_kernel<<<NROWS/256, 256>>>(zg, cb, zq, idxo);

    // decoder (tensor cores, double-buffered)
    mma_gemm<1><<<dim3(H2D/128,   NROWS/128), 256, MMA_DSM>>>(zq, w1h, w1l, bd1, h2,   LATD, H2D);
    mma_gemm<1><<<dim3(H1D/128,   NROWS/128), 256, MMA_DSM>>>(h2, w2h, w2l, bd2, h1,   H2D,  H1D);
    mma_gemm<2><<<dim3(IN_DIM/128,NROWS/128), 256, MMA_DSM>>>(h1, w3h, w3l, bd3, xrec, H1D,  IN_DIM);

    fin_kernel<<<1, 1>>>(losso);
}

// round 15
// speedup vs baseline: 1.3459x; 1.3335x over previous
#include <cuda_runtime.h>
#include <cuda_bf16.h>
#include <math.h>
#include <stdint.h>

#define NROWS 65536
#define IN_DIM 1024
#define H1D 512
#define H2D 256
#define LATD 64
#define NCODE 1024
#define COMMIT_BETA 0.25
#define TAU 2e-4f

// -------- scratch (device globals: allocation-free per harness rules) --------
__device__ float g_h1[(size_t)NROWS * H1D];   // h1 approx, then repair h1 (dense)
__device__ float g_h2[(size_t)NROWS * H2D];   // h2 approx, then repair h2 (dense)
__device__ float g_zg[(size_t)NROWS * LATD];  // repair exact z (dense)
__device__ float g_t1[NCODE * H2D];           // decoder table L1 (1 MB)
__device__ float g_t2[NCODE * H1D];           // decoder table L2 (2 MB)
__device__ float g_t3[NCODE * IN_DIM];        // decoder table L3 (4 MB)
__device__ int   g_idx[NROWS];
__device__ int   g_rlist[NROWS];
__device__ int   g_rcnt;
__device__ float g_esq[NCODE];
__device__ double g_loss;
// bf16 split encoder weights, transposed to [N, K]
__device__ __nv_bfloat16 g_e1h[H1D * IN_DIM], g_e1l[H1D * IN_DIM];
__device__ __nv_bfloat16 g_e2h[H2D * H1D],    g_e2l[H2D * H1D];

__device__ __forceinline__ uint32_t smem_u32(const void* p) {
    uint32_t a;
    asm("{ .reg .u64 t; cvta.to.shared.u64 t, %1; cvt.u32.u64 %0, t; }"
        : "=r"(a) : "l"(p));
    return a;
}
__device__ __forceinline__ void ldsm_x4(uint32_t& r0, uint32_t& r1,
                                        uint32_t& r2, uint32_t& r3, uint32_t addr) {
    asm volatile("ldmatrix.sync.aligned.m8n8.x4.shared.b16 {%0,%1,%2,%3}, [%4];"
                 : "=r"(r0), "=r"(r1), "=r"(r2), "=r"(r3) : "r"(addr));
}
__device__ __forceinline__ void mma_bf16(float* c, const uint32_t* a, const uint32_t* b) {
    asm volatile("mma.sync.aligned.m16n8k16.row.col.f32.bf16.bf16.f32 "
        "{%0,%1,%2,%3},{%4,%5,%6,%7},{%8,%9},{%0,%1,%2,%3};"
        : "+f"(c[0]), "+f"(c[1]), "+f"(c[2]), "+f"(c[3])
        : "r"(a[0]), "r"(a[1]), "r"(a[2]), "r"(a[3]), "r"(b[0]), "r"(b[1]));
}

// ============================================================================
// Warp-MMA bf16 GEMM, 3-term split: C += Ah*Bh + Al*Bh + Ah*Bl (fp32 acc).
// Double-buffered dynamic smem. CTA 128x128, BK=32, 8 warps. ACT 1=relu.
// ============================================================================
#define MMA_BUFB 40960u
#define MMA_DSM  (2 * 40960)

template<int ACT>
__global__ __launch_bounds__(256, 1)
void mma_gemm(const float* __restrict__ A,
              const __nv_bfloat16* __restrict__ Wh,
              const __nv_bfloat16* __restrict__ Wl,
              const float* __restrict__ bias, float* __restrict__ C,
              int K, int N)
{
    extern __shared__ char dsm[];
    const uint32_t sb = smem_u32(dsm);

    const int tid = threadIdx.x;
    const int lane = tid & 31, wid = tid >> 5;
    const int m0 = blockIdx.y * 128, n0 = blockIdx.x * 128;
    const int wm = (wid & 1) * 64, wn = (wid >> 1) * 32;

    float acc[4][4][4];
    #pragma unroll
    for (int i = 0; i < 4; i++)
        #pragma unroll
        for (int j = 0; j < 4; j++)
            #pragma unroll
            for (int q = 0; q < 4; q++) acc[i][j][q] = 0.f;

    const int arow = tid >> 1;
    const int aq = tid & 1;

    float4 ra[4];
    uint4 rbh[2], rbl[2];

    auto loadG = [&](int k0) {
        const float4* ap = reinterpret_cast<const float4*>(
            &A[(size_t)(m0 + arow) * K + k0 + aq * 16]);
        #pragma unroll
        for (int j = 0; j < 4; j++) ra[j] = ap[j];
        const uint4* bph = reinterpret_cast<const uint4*>(
            &Wh[(size_t)(n0 + arow) * K + k0]);
        const uint4* bpl = reinterpret_cast<const uint4*>(
            &Wl[(size_t)(n0 + arow) * K + k0]);
        #pragma unroll
        for (int j = 0; j < 2; j++) {
            rbh[j] = bph[aq * 2 + j];
            rbl[j] = bpl[aq * 2 + j];
        }
    };
    auto storeS = [&](int p) {
        const uint32_t b = sb + (uint32_t)p * MMA_BUFB;
        const uint32_t aAh = b, aAl = b + 10240u;
        const uint32_t aBh = b + 20480u, aBl = b + 30720u;
        #pragma unroll
        for (int j = 0; j < 4; j++) {
            float4 v = ra[j];
            __nv_bfloat16 h0 = __float2bfloat16_rn(v.x);
            __nv_bfloat16 h1 = __float2bfloat16_rn(v.y);
            __nv_bfloat16 h2 = __float2bfloat16_rn(v.z);
            __nv_bfloat16 h3 = __float2bfloat16_rn(v.w);
            __nv_bfloat16 l0 = __float2bfloat16_rn(v.x - __bfloat162float(h0));
            __nv_bfloat16 l1 = __float2bfloat16_rn(v.y - __bfloat162float(h1));
            __nv_bfloat16 l2 = __float2bfloat16_rn(v.z - __bfloat162float(h2));
            __nv_bfloat16 l3 = __float2bfloat16_rn(v.w - __bfloat162float(h3));
            uint32_t hp0 = (uint32_t)__bfloat16_as_ushort(h0) |
                           ((uint32_t)__bfloat16_as_ushort(h1) << 16);
            uint32_t hp1 = (uint32_t)__bfloat16_as_ushort(h2) |
                           ((uint32_t)__bfloat16_as_ushort(h3) << 16);
            uint32_t lp0 = (uint32_t)__bfloat16_as_ushort(l0) |
                           ((uint32_t)__bfloat16_as_ushort(l1) << 16);
            uint32_t lp1 = (uint32_t)__bfloat16_as_ushort(l2) |
                           ((uint32_t)__bfloat16_as_ushort(l3) << 16);
            uint32_t off = (uint32_t)(arow * 80 + aq * 32 + j * 8);
            asm volatile("st.shared.v2.b32 [%0], {%1,%2};"
                         :: "r"(aAh + off), "r"(hp0), "r"(hp1) : "memory");
            asm volatile("st.shared.v2.b32 [%0], {%1,%2};"
                         :: "r"(aAl + off), "r"(lp0), "r"(lp1) : "memory");
        }
        #pragma unroll
        for (int j = 0; j < 2; j++) {
            uint32_t off = (uint32_t)(arow * 80 + (aq * 2 + j) * 16);
            asm volatile("st.shared.v4.b32 [%0], {%1,%2,%3,%4};"
                         :: "r"(aBh + off), "r"(rbh[j].x), "r"(rbh[j].y),
                            "r"(rbh[j].z), "r"(rbh[j].w) : "memory");
            asm volatile("st.shared.v4.b32 [%0], {%1,%2,%3,%4};"
                         :: "r"(aBl + off), "r"(rbl[j].x), "r"(rbl[j].y),
                            "r"(rbl[j].z), "r"(rbl[j].w) : "memory");
        }
    };
    auto compute = [&](int p) {
        const uint32_t b = sb + (uint32_t)p * MMA_BUFB;
        const uint32_t aAh = b, aAl = b + 10240u;
        const uint32_t aBh = b + 20480u, aBl = b + 30720u;
        #pragma unroll
        for (int ks = 0; ks < 2; ks++) {
            uint32_t ah[4][4], al[4][4], bh[4][2], bl[4][2];
            const int arl = lane & 15;
            const uint32_t ab = (uint32_t)((lane >> 4) * 16 + ks * 32);
            #pragma unroll
            for (int mt = 0; mt < 4; mt++) {
                uint32_t off = (uint32_t)((wm + mt * 16 + arl) * 80) + ab;
                ldsm_x4(ah[mt][0], ah[mt][1], ah[mt][2], ah[mt][3], aAh + off);
                ldsm_x4(al[mt][0], al[mt][1], al[mt][2], al[mt][3], aAl + off);
            }
            const int bn = (lane & 7) + ((lane >> 4) << 3);
            const uint32_t bb = (uint32_t)(((lane >> 3) & 1) * 16 + ks * 32);
            #pragma unroll
            for (int np = 0; np < 2; np++) {
                uint32_t off = (uint32_t)((wn + np * 16 + bn) * 80) + bb;
                uint32_t r0, r1, r2, r3;
                ldsm_x4(r0, r1, r2, r3, aBh + off);
                bh[np*2][0] = r0; bh[np*2][1] = r1;
                bh[np*2+1][0] = r2; bh[np*2+1][1] = r3;
                ldsm_x4(r0, r1, r2, r3, aBl + off);
                bl[np*2][0] = r0; bl[np*2][1] = r1;
                bl[np*2+1][0] = r2; bl[np*2+1][1] = r3;
            }
            #pragma unroll
            for (int mt = 0; mt < 4; mt++)
                #pragma unroll
                for (int nt = 0; nt < 4; nt++) {
                    mma_bf16(acc[mt][nt], ah[mt], bh[nt]);
                    mma_bf16(acc[mt][nt], al[mt], bh[nt]);
                    mma_bf16(acc[mt][nt], ah[mt], bl[nt]);
                }
        }
    };

    const int ntc = K >> 5;
    loadG(0);
    storeS(0);
    __syncthreads();
    #pragma unroll 1
    for (int ch = 0; ch < ntc - 1; ch++) {
        loadG((ch + 1) << 5);
        compute(ch & 1);
        storeS((ch + 1) & 1);
        __syncthreads();
    }
    compute((ntc - 1) & 1);

    #pragma unroll
    for (int nt = 0; nt < 4; nt++) {
        const int col = n0 + wn + nt * 8 + (lane & 3) * 2;
        const float2 bv = *reinterpret_cast<const float2*>(&bias[col]);
        #pragma unroll
        for (int mt = 0; mt < 4; mt++) {
            const int r0 = m0 + wm + mt * 16 + (lane >> 2);
            float u0 = acc[mt][nt][0] + bv.x;
            float u1 = acc[mt][nt][1] + bv.y;
            float u2 = acc[mt][nt][2] + bv.x;
            float u3 = acc[mt][nt][3] + bv.y;
            if (ACT == 1) {
                u0 = fmaxf(u0, 0.f); u1 = fmaxf(u1, 0.f);
                u2 = fmaxf(u2, 0.f); u3 = fmaxf(u3, 0.f);
            } else {
                u0 = tanhf(u0); u1 = tanhf(u1);
                u2 = tanhf(u2); u3 = tanhf(u3);
            }
            *reinterpret_cast<float2*>(&C[(size_t)r0 * N + col]) = make_float2(u0, u1);
            *reinterpret_cast<float2*>(&C[(size_t)(r0 + 8) * N + col]) = make_float2(u2, u3);
        }
    }
}

// ============================================================================
// weight split: W[K,N] f32 -> Wh/Wl [N,K] bf16 (transposed)
// ============================================================================
__global__ void wsplit_kernel(const float* __restrict__ W,
                              __nv_bfloat16* __restrict__ Wh,
                              __nv_bfloat16* __restrict__ Wl, int K, int N)
{
    int i = blockIdx.x * 256 + threadIdx.x;
    if (i >= K * N) return;
    int n = i / K, k = i - n * K;
    float w = W[(size_t)k * N + n];
    __nv_bfloat16 h = __float2bfloat16_rn(w);
    Wh[i] = h;
    Wl[i] = __float2bfloat16_rn(w - __bfloat162float(h));
}

// ============================================================================
// Scalar fp32 SGEMM, bitwise-exact sequential-k.
// MODE 0: normal. MODE 1: dense rows, count early-out. MODE 2: A rows via rlist.
// ============================================================================
template<int BM,int BN,int BK,int TM,int TN,int ACT,int MODE>
__global__ __launch_bounds__((BM/TM)*(BN/TN), 2)
void gemm_bias_act(const float* __restrict__ A, const float* __restrict__ B,
                   const float* __restrict__ bias, float* __restrict__ C,
                   int M, int N, int K,
                   const int* __restrict__ rows, const int* __restrict__ cntp)
{
    constexpr int NT = (BM/TM)*(BN/TN);
    constexpr int LA = (BM*BK)/(NT*4);
    constexpr int LB = (BK*BN)/(NT*4);

    __shared__ __align__(16) float As[2][BK][BM];
    __shared__ __align__(16) float Bs[2][BK][BN];
    __shared__ int srow[BM];

    const int tid = threadIdx.x;
    const int m0 = blockIdx.y * BM;
    const int n0 = blockIdx.x * BN;
    const int tx = tid % (BN/TN);
    const int ty = tid / (BN/TN);

    if (MODE >= 1) {
        const int cn = *cntp;
        if (cn == 0 || m0 >= cn) return;
        if (MODE == 2) {
            if (tid < BM) {
                int r = m0 + tid;
                srow[tid] = rows[r < cn ? r : (cn - 1)];
            }
            __syncthreads();
        }
    }

    float acc[TM][TN];
    #pragma unroll
    for (int i = 0; i < TM; i++)
        #pragma unroll
        for (int j = 0; j < TN; j++) acc[i][j] = 0.f;

    float4 ra[LA], rb[LB];

    #pragma unroll
    for (int j = 0; j < LA; j++) {
        int i = (tid + j*NT) * 4;
        int r = i / BK, c = i % BK;
        const int ar = (MODE == 2) ? srow[r] : (m0 + r);
        ra[j] = *reinterpret_cast<const float4*>(&A[(size_t)ar*K + c]);
    }
    #pragma unroll
    for (int j = 0; j < LB; j++) {
        int i = (tid + j*NT) * 4;
        int r = i / BN, c = i % BN;
        rb[j] = *reinterpret_cast<const float4*>(&B[(size_t)r*N + n0 + c]);
    }
    #pragma unroll
    for (int j = 0; j < LA; j++) {
        int i = (tid + j*NT) * 4;
        int r = i / BK, c = i % BK;
        As[0][c+0][r] = ra[j].x; As[0][c+1][r] = ra[j].y;
        As[0][c+2][r] = ra[j].z; As[0][c+3][r] = ra[j].w;
    }
    #pragma unroll
    for (int j = 0; j < LB; j++) {
        int i = (tid + j*NT) * 4;
        int r = i / BN, c = i % BN;
        *reinterpret_cast<float4*>(&Bs[0][r][c]) = rb[j];
    }
    __syncthreads();

    const int ntiles = K / BK;
    #pragma unroll 1
    for (int t = 1; t < ntiles; t++) {
        const int k0 = t * BK;
        #pragma unroll
        for (int j = 0; j < LA; j++) {
            int i = (tid + j*NT) * 4;
            int r = i / BK, c = i % BK;
            const int ar = (MODE == 2) ? srow[r] : (m0 + r);
            ra[j] = *reinterpret_cast<const float4*>(&A[(size_t)ar*K + k0 + c]);
        }
        #pragma unroll
        for (int j = 0; j < LB; j++) {
            int i = (tid + j*NT) * 4;
            int r = i / BN, c = i % BN;
            rb[j] = *reinterpret_cast<const float4*>(&B[(size_t)(k0 + r)*N + n0 + c]);
        }
        const int cur = (t - 1) & 1;
        #pragma unroll
        for (int k = 0; k < BK; k++) {
            float a[TM], b[TN];
            #pragma unroll
            for (int i = 0; i < TM; i += 4) {
                float4 v = *reinterpret_cast<const float4*>(&As[cur][k][ty*TM + i]);
                a[i] = v.x; a[i+1] = v.y; a[i+2] = v.z; a[i+3] = v.w;
            }
            #pragma unroll
            for (int j = 0; j < TN; j += 4) {
                float4 v = *reinterpret_cast<const float4*>(&Bs[cur][k][tx*TN + j]);
                b[j] = v.x; b[j+1] = v.y; b[j+2] = v.z; b[j+3] = v.w;
            }
            #pragma unroll
            for (int i = 0; i < TM; i++)
                #pragma unroll
                for (int j = 0; j < TN; j++)
                    acc[i][j] = fmaf(a[i], b[j], acc[i][j]);
        }
        const int nxt = t & 1;
        #pragma unroll
        for (int j = 0; j < LA; j++) {
            int i = (tid + j*NT) * 4;
            int r = i / BK, c = i % BK;
            As[nxt][c+0][r] = ra[j].x; As[nxt][c+1][r] = ra[j].y;
            As[nxt][c+2][r] = ra[j].z; As[nxt][c+3][r] = ra[j].w;
        }
        #pragma unroll
        for (int j = 0; j < LB; j++) {
            int i = (tid + j*NT) * 4;
            int r = i / BN, c = i % BN;
            *reinterpret_cast<float4*>(&Bs[nxt][r][c]) = rb[j];
        }
        __syncthreads();
    }
    {
        const int cur = (ntiles - 1) & 1;
        #pragma unroll
        for (int k = 0; k < BK; k++) {
            float a[TM], b[TN];
            #pragma unroll
            for (int i = 0; i < TM; i += 4) {
                float4 v = *reinterpret_cast<const float4*>(&As[cur][k][ty*TM + i]);
                a[i] = v.x; a[i+1] = v.y; a[i+2] = v.z; a[i+3] = v.w;
            }
            #pragma unroll
            for (int j = 0; j < TN; j += 4) {
                float4 v = *reinterpret_cast<const float4*>(&Bs[cur][k][tx*TN + j]);
                b[j] = v.x; b[j+1] = v.y; b[j+2] = v.z; b[j+3] = v.w;
            }
            #pragma unroll
            for (int i = 0; i < TM; i++)
                #pragma unroll
                for (int j = 0; j < TN; j++)
                    acc[i][j] = fmaf(a[i], b[j], acc[i][j]);
        }
    }

    float bv[TN];
    #pragma unroll
    for (int j = 0; j < TN; j++) bv[j] = bias[n0 + tx*TN + j];
    #pragma unroll
    for (int i = 0; i < TM; i++) {
        const int row = m0 + ty*TM + i;
        float* Cp = &C[(size_t)row*N + n0 + tx*TN];
        #pragma unroll
        for (int j = 0; j < TN; j += 4) {
            float vv[4];
            #pragma unroll
            for (int q = 0; q < 4; q++) {
                float u = acc[i][j+q] + bv[j+q];
                if (ACT == 1) u = fmaxf(u, 0.f);
                else if (ACT == 2) u = tanhf(u);
                vv[q] = u;
            }
            *reinterpret_cast<float4*>(&Cp[j]) = make_float4(vv[0], vv[1], vv[2], vv[3]);
        }
    }
}

// ============================================================================
// prep: codebook squared norms + zero loss + zero repair count
// ============================================================================
__global__ void prep_kernel(const float* __restrict__ cb)
{
    const int c = blockIdx.x * blockDim.x + threadIdx.x;
    if (c == 0) { g_loss = 0.0; g_rcnt = 0; }
    if (c < NCODE) {
        const float* p = &cb[(size_t)c * LATD];
        float s = 0.f;
        #pragma unroll
        for (int i = 0; i < LATD; i++) s = fmaf(p[i], p[i], s);
        g_esq[c] = s;
    }
}

// ============================================================================
// Approx VQ: reference-rounding dists on approx z; top-2 tracked; ambiguous
// rows (gap < TAU) -> repair list. Writes int idx, float idx, loss.
// ============================================================================
__global__ __launch_bounds__(256)
void vq_approx_kernel(const float* __restrict__ z, const float* __restrict__ cb,
                      int* __restrict__ idx_i, float* __restrict__ idx_out)
{
    __shared__ __align__(16) float4 sc[128 * 16];
    __shared__ float sesq[128];
    __shared__ float wsum[8];

    const int tid = threadIdx.x;
    const int row = blockIdx.x * 256 + tid;

    float4 zr[16];
    const float4* zp = reinterpret_cast<const float4*>(&z[(size_t)row * LATD]);
    #pragma unroll
    for (int i = 0; i < 16; i++) zr[i] = zp[i];

    float z_sq = 0.f;
    #pragma unroll
    for (int i = 0; i < 16; i++) {
        z_sq = fmaf(zr[i].x, zr[i].x, z_sq);
        z_sq = fmaf(zr[i].y, zr[i].y, z_sq);
        z_sq = fmaf(zr[i].z, zr[i].z, z_sq);
        z_sq = fmaf(zr[i].w, zr[i].w, z_sq);
    }

    float best = 3.4028235e38f, second = 3.4028235e38f;
    int bi = 0;
    for (int c0 = 0; c0 < NCODE; c0 += 128) {
        __syncthreads();
        const float4* cp = reinterpret_cast<const float4*>(&cb[(size_t)c0 * LATD]);
        #pragma unroll
        for (int j = 0; j < 8; j++) sc[tid + j*256] = cp[tid + j*256];
        if (tid < 128) sesq[tid] = g_esq[c0 + tid];
        __syncthreads();

        #pragma unroll 4
        for (int c = 0; c < 128; c++) {
            const float4* e = &sc[c * 16];
            float acc = 0.f;
            #pragma unroll
            for (int i = 0; i < 16; i++) {
                float4 v = e[i];
                acc = fmaf(zr[i].x, v.x, acc);
                acc = fmaf(zr[i].y, v.y, acc);
                acc = fmaf(zr[i].z, v.z, acc);
                acc = fmaf(zr[i].w, v.w, acc);
            }
            float t = z_sq - 2.0f * acc;
            float d = t + sesq[c];
            if (d < best) { second = best; best = d; bi = c0 + c; }
            else if (d < second) { second = d; }
        }
    }

    if (second - best < TAU) {
        int p = atomicAdd(&g_rcnt, 1);
        g_rlist[p] = row;
    }

    const float4* ep = reinterpret_cast<const float4*>(&cb[(size_t)bi * LATD]);
    float ls = 0.f;
    #pragma unroll
    for (int i = 0; i < 16; i++) {
        float4 e = ep[i];
        float dx = e.x - zr[i].x, dy = e.y - zr[i].y;
        float dz = e.z - zr[i].z, dw = e.w - zr[i].w;
        ls += dx*dx + dy*dy + dz*dz + dw*dw;
    }
    idx_i[row] = bi;
    idx_out[row] = (float)bi;

    #pragma unroll
    for (int o = 16; o > 0; o >>= 1) ls += __shfl_down_sync(0xffffffffu, ls, o);
    if ((tid & 31) == 0) wsum[tid >> 5] = ls;
    __syncthreads();
    if (tid == 0) {
        float s = 0.f;
        #pragma unroll
        for (int i = 0; i < 8; i++) s += wsum[i];
        atomicAdd(&g_loss, (double)s);
    }
}

// ============================================================================
// Repair VQ: exact argmin on exact z (dense zg rows), scatter idx.
// ============================================================================
__global__ __launch_bounds__(256)
void vq_repair_kernel(const float* __restrict__ zg, const float* __restrict__ cb,
                      int* __restrict__ idx_i, float* __restrict__ idx_out)
{
    __shared__ __align__(16) float4 sc[128 * 16];
    __shared__ float sesq[128];

    const int cn = g_rcnt;
    const int m0 = blockIdx.x * 256;
    if (cn == 0 || m0 >= cn) return;

    const int tid = threadIdx.x;
    int r = m0 + tid;
    if (r >= cn) r = cn - 1;

    float4 zr[16];
    const float4* zp = reinterpret_cast<const float4*>(&zg[(size_t)r * LATD]);
    #pragma unroll
    for (int i = 0; i < 16; i++) zr[i] = zp[i];

    float z_sq = 0.f;
    #pragma unroll
    for (int i = 0; i < 16; i++) {
        z_sq = fmaf(zr[i].x, zr[i].x, z_sq);
        z_sq = fmaf(zr[i].y, zr[i].y, z_sq);
        z_sq = fmaf(zr[i].z, zr[i].z, z_sq);
        z_sq = fmaf(zr[i].w, zr[i].w, z_sq);
    }

    float best = 3.4028235e38f;
    int bi = 0;
    for (int c0 = 0; c0 < NCODE; c0 += 128) {
        __syncthreads();
        const float4* cp = reinterpret_cast<const float4*>(&cb[(size_t)c0 * LATD]);
        #pragma unroll
        for (int j = 0; j < 8; j++) sc[tid + j*256] = cp[tid + j*256];
        if (tid < 128) sesq[tid] = g_esq[c0 + tid];
        __syncthreads();

        #pragma unroll 4
        for (int c = 0; c < 128; c++) {
            const float4* e = &sc[c * 16];
            float acc = 0.f;
            #pragma unroll
            for (int i = 0; i < 16; i++) {
                float4 v = e[i];
                acc = fmaf(zr[i].x, v.x, acc);
                acc = fmaf(zr[i].y, v.y, acc);
                acc = fmaf(zr[i].z, v.z, acc);
                acc = fmaf(zr[i].w, v.w, acc);
            }
            float t = z_sq - 2.0f * acc;
            float d = t + sesq[c];
            if (d < best) { best = d; bi = c0 + c; }
        }
    }

    const int orow = g_rlist[r];
    idx_i[orow] = bi;
    idx_out[orow] = (float)bi;
}

// ============================================================================
// gather: x_recon[row] = t3[idx[row]]  (4MB table, L2-resident; coalesced out)
// ============================================================================
__global__ __launch_bounds__(256)
void gather_kernel(const float* __restrict__ table, const int* __restrict__ idx,
                   float* __restrict__ outp)
{
    const int row  = blockIdx.x * 8 + (threadIdx.x >> 5);
    const int lane = threadIdx.x & 31;
    const float4* src = reinterpret_cast<const float4*>(
        &table[(size_t)idx[row] * IN_DIM]);
    float4* dst = reinterpret_cast<float4*>(&outp[(size_t)row * IN_DIM]);
    #pragma unroll
    for (int j = 0; j < 8; j++) dst[lane + 32*j] = src[lane + 32*j];
}

__global__ void fin_kernel(float* __restrict__ loss_out)
{
    loss_out[0] = (float)(COMMIT_BETA * g_loss / ((double)NROWS * LATD));
}

// ============================================================================
// launch  (mma_e1 placed at launch index 3 — the slot ncu actually captures)
// ============================================================================
extern "C" void kernel_launch(void* const* d_in, const int* in_sizes, int n_in,
                              void* d_out, int out_size)
{
    const float* x   = (const float*)d_in[0];
    const float* We1 = (const float*)d_in[1];
    const float* be1 = (const float*)d_in[2];
    const float* We2 = (const float*)d_in[3];
    const float* be2 = (const float*)d_in[4];
    const float* We3 = (const float*)d_in[5];
    const float* be3 = (const float*)d_in[6];
    const float* cb  = (const float*)d_in[7];
    const float* Wd1 = (const float*)d_in[8];
    const float* bd1 = (const float*)d_in[9];
    const float* Wd2 = (const float*)d_in[10];
    const float* bd2 = (const float*)d_in[11];
    const float* Wd3 = (const float*)d_in[12];
    const float* bd3 = (const float*)d_in[13];

    float* out   = (float*)d_out;
    float* xrec  = out;
    float* zout  = out + (size_t)NROWS * IN_DIM;
    float* idxo  = zout + (size_t)NROWS * LATD;
    float* losso = idxo + NROWS;

    float *h1, *h2, *zg, *t1, *t2, *t3;
    int *idxi, *rlist, *rcnt;
    cudaGetSymbolAddress((void**)&h1, g_h1);
    cudaGetSymbolAddress((void**)&h2, g_h2);
    cudaGetSymbolAddress((void**)&zg, g_zg);
    cudaGetSymbolAddress((void**)&t1, g_t1);
    cudaGetSymbolAddress((void**)&t2, g_t2);
    cudaGetSymbolAddress((void**)&t3, g_t3);
    cudaGetSymbolAddress((void**)&idxi, g_idx);
    cudaGetSymbolAddress((void**)&rlist, g_rlist);
    cudaGetSymbolAddress((void**)&rcnt, g_rcnt);
    __nv_bfloat16 *e1h, *e1l, *e2h, *e2l;
    cudaGetSymbolAddress((void**)&e1h, g_e1h);
    cudaGetSymbolAddress((void**)&e1l, g_e1l);
    cudaGetSymbolAddress((void**)&e2h, g_e2h);
    cudaGetSymbolAddress((void**)&e2l, g_e2l);

    cudaFuncSetAttribute(mma_gemm<1>, cudaFuncAttributeMaxDynamicSharedMemorySize, MMA_DSM);

    // 0-2: prep + encoder weight splits
    prep_kernel<<<4, 256>>>(cb);
    wsplit_kernel<<<(IN_DIM*H1D + 255)/256, 256>>>(We1, e1h, e1l, IN_DIM, H1D);
    wsplit_kernel<<<(H1D*H2D  + 255)/256, 256>>>(We2, e2h, e2l, H1D, H2D);

    // 3: e1 on tensor cores (profiling target)
    mma_gemm<1><<<dim3(H1D/128, NROWS/128), 256, MMA_DSM>>>(x, e1h, e1l, be1, h1, IN_DIM, H1D);

    // decoder lookup tables (exact fp32; tiny: 1.4 GF total)
    gemm_bias_act<128,128,16,8,8,1,0><<<dim3(H2D/128, NCODE/128), 256>>>(
        cb, Wd1, bd1, t1, NCODE, H2D, LATD, nullptr, nullptr);
    gemm_bias_act<128,128,16,8,8,1,0><<<dim3(H1D/128, NCODE/128), 256>>>(
        t1, Wd2, bd2, t2, NCODE, H1D, H2D, nullptr, nullptr);
    gemm_bias_act<128,128,16,8,8,2,0><<<dim3(IN_DIM/128, NCODE/128), 256>>>(
        t2, Wd3, bd3, t3, NCODE, IN_DIM, H1D, nullptr, nullptr);

    // rest of approx encoder
    mma_gemm<1><<<dim3(H2D/128, NROWS/128), 256, MMA_DSM>>>(h1, e2h, e2l, be2, h2, H1D, H2D);
    gemm_bias_act<128,64,16,8,4,0,0><<<dim3(1, NROWS/128), 256>>>(
        h2, We3, be3, zout, NROWS, LATD, H2D, nullptr, nullptr);

    // approx VQ + ambiguity detection
    vq_approx_kernel<<<NROWS/256, 256>>>(zout, cb, idxi, idxo);

    // exact repair chain (bitwise fp32, only listed rows do real work)
    gemm_bias_act<128,128,16,8,8,1,2><<<dim3(H1D/128, NROWS/128), 256>>>(
        x,  We1, be1, h1, NROWS, H1D, IN_DIM, rlist, rcnt);
    gemm_bias_act<128,128,16,8,8,1,1><<<dim3(H2D/128, NROWS/128), 256>>>(
        h1, We2, be2, h2, NROWS, H2D, H1D, nullptr, rcnt);
    gemm_bias_act<128,64,16,8,4,0,1><<<dim3(1, NROWS/128), 256>>>(
        h2, We3, be3, zg, NROWS, LATD, H2D, nullptr, rcnt);
    vq_repair_kernel<<<NROWS/256, 256>>>(zg, cb, idxi, idxo);

    // x_recon = decoder-table gather on repaired indices
    gather_kernel<<<NROWS/8, 256>>>(t3, idxi, xrec);

    fin_kernel<<<1, 1>>>(losso);
}

// round 17
// speedup vs baseline: 1.4313x; 1.0635x over previous
#include <cuda_runtime.h>
#include <cuda_bf16.h>
#include <math.h>
#include <stdint.h>

#define NROWS 65536
#define IN_DIM 1024
#define H1D 512
#define H2D 256
#define LATD 64
#define NCODE 1024
#define COMMIT_BETA 0.25
#define TAU 2e-4f

// -------- scratch (device globals: allocation-free per harness rules) --------
__device__ float g_h1[(size_t)NROWS * H1D];
__device__ float g_h2[(size_t)NROWS * H2D];
__device__ float g_zg[(size_t)NROWS * LATD];
__device__ float g_t1[NCODE * H2D];
__device__ float g_t2[NCODE * H1D];
__device__ float g_t3[NCODE * IN_DIM];
__device__ int   g_idx[NROWS];
__device__ int   g_rlist[NROWS];
__device__ int   g_rcnt;
__device__ float g_esq[NCODE];
__device__ double g_loss;
__device__ __nv_bfloat16 g_e1h[H1D * IN_DIM], g_e1l[H1D * IN_DIM];
__device__ __nv_bfloat16 g_e2h[H2D * H1D],    g_e2l[H2D * H1D];

__device__ __forceinline__ uint32_t smem_u32(const void* p) {
    uint32_t a;
    asm("{ .reg .u64 t; cvta.to.shared.u64 t, %1; cvt.u32.u64 %0, t; }"
        : "=r"(a) : "l"(p));
    return a;
}
__device__ __forceinline__ void ldsm_x4(uint32_t& r0, uint32_t& r1,
                                        uint32_t& r2, uint32_t& r3, uint32_t addr) {
    asm volatile("ldmatrix.sync.aligned.m8n8.x4.shared.b16 {%0,%1,%2,%3}, [%4];"
                 : "=r"(r0), "=r"(r1), "=r"(r2), "=r"(r3) : "r"(addr));
}
__device__ __forceinline__ void mma_bf16(float* c, const uint32_t* a, const uint32_t* b) {
    asm volatile("mma.sync.aligned.m16n8k16.row.col.f32.bf16.bf16.f32 "
        "{%0,%1,%2,%3},{%4,%5,%6,%7},{%8,%9},{%0,%1,%2,%3};"
        : "+f"(c[0]), "+f"(c[1]), "+f"(c[2]), "+f"(c[3])
        : "r"(a[0]), "r"(a[1]), "r"(a[2]), "r"(a[3]), "r"(b[0]), "r"(b[1]));
}
__device__ __forceinline__ void cp_async16(uint32_t dst, const void* src) {
    asm volatile("cp.async.ca.shared.global [%0], [%1], 16;"
                 :: "r"(dst), "l"(src) : "memory");
}
#define CP_COMMIT() asm volatile("cp.async.commit_group;" ::: "memory")
#define CP_WAIT0()  asm volatile("cp.async.wait_group 0;" ::: "memory")

// ============================================================================
// Warp-MMA bf16 GEMM, 3-term split: C += Ah*Bh + Ah*Bl + Al*Bh (fp32 acc).
// 2 CTAs/SM (__launch_bounds__(256,2)); B tiles via cp.async (pre-split bf16);
// A split in-kernel; fragment-reuse keeps regs <=128. Double-buffered smem.
// CTA 128x128, BK=32, 8 warps (2x4 -> warp tile 64x32). ACT: 1=relu.
// ============================================================================
#define MMA_BUFB 40960u
#define MMA_DSM  (2 * 40960)

template<int ACT>
__global__ __launch_bounds__(256, 2)
void mma_gemm(const float* __restrict__ A,
              const __nv_bfloat16* __restrict__ Wh,
              const __nv_bfloat16* __restrict__ Wl,
              const float* __restrict__ bias, float* __restrict__ C,
              int K, int N)
{
    extern __shared__ char dsm[];
    const uint32_t sb = smem_u32(dsm);

    const int tid = threadIdx.x;
    const int lane = tid & 31, wid = tid >> 5;
    const int m0 = blockIdx.y * 128, n0 = blockIdx.x * 128;
    const int wm = (wid & 1) * 64, wn = (wid >> 1) * 32;

    float acc[4][4][4];
    #pragma unroll
    for (int i = 0; i < 4; i++)
        #pragma unroll
        for (int j = 0; j < 4; j++)
            #pragma unroll
            for (int q = 0; q < 4; q++) acc[i][j][q] = 0.f;

    const int arow = tid >> 1;
    const int aq = tid & 1;

    float4 ra[4];

    // B tiles: gmem (pre-split bf16 [N,K]) -> smem via cp.async, no registers
    auto cpasyncB = [&](int k0, int p) {
        const uint32_t b = sb + (uint32_t)p * MMA_BUFB;
        const uint32_t aBh = b + 20480u, aBl = b + 30720u;
        const char* srch = (const char*)&Wh[(size_t)(n0 + arow) * K + k0];
        const char* srcl = (const char*)&Wl[(size_t)(n0 + arow) * K + k0];
        #pragma unroll
        for (int j = 0; j < 2; j++) {
            const int u = aq * 2 + j;
            uint32_t off = (uint32_t)(arow * 80 + u * 16);
            cp_async16(aBh + off, srch + u * 16);
            cp_async16(aBl + off, srcl + u * 16);
        }
    };
    auto loadG = [&](int k0) {
        const float4* ap = reinterpret_cast<const float4*>(
            &A[(size_t)(m0 + arow) * K + k0 + aq * 16]);
        #pragma unroll
        for (int j = 0; j < 4; j++) ra[j] = ap[j];
    };
    auto storeS = [&](int p) {
        const uint32_t b = sb + (uint32_t)p * MMA_BUFB;
        const uint32_t aAh = b, aAl = b + 10240u;
        #pragma unroll
        for (int j = 0; j < 4; j++) {
            float4 v = ra[j];
            __nv_bfloat16 h0 = __float2bfloat16_rn(v.x);
            __nv_bfloat16 h1 = __float2bfloat16_rn(v.y);
            __nv_bfloat16 h2 = __float2bfloat16_rn(v.z);
            __nv_bfloat16 h3 = __float2bfloat16_rn(v.w);
            __nv_bfloat16 l0 = __float2bfloat16_rn(v.x - __bfloat162float(h0));
            __nv_bfloat16 l1 = __float2bfloat16_rn(v.y - __bfloat162float(h1));
            __nv_bfloat16 l2 = __float2bfloat16_rn(v.z - __bfloat162float(h2));
            __nv_bfloat16 l3 = __float2bfloat16_rn(v.w - __bfloat162float(h3));
            uint32_t hp0 = (uint32_t)__bfloat16_as_ushort(h0) |
                           ((uint32_t)__bfloat16_as_ushort(h1) << 16);
            uint32_t hp1 = (uint32_t)__bfloat16_as_ushort(h2) |
                           ((uint32_t)__bfloat16_as_ushort(h3) << 16);
            uint32_t lp0 = (uint32_t)__bfloat16_as_ushort(l0) |
                           ((uint32_t)__bfloat16_as_ushort(l1) << 16);
            uint32_t lp1 = (uint32_t)__bfloat16_as_ushort(l2) |
                           ((uint32_t)__bfloat16_as_ushort(l3) << 16);
            uint32_t off = (uint32_t)(arow * 80 + aq * 32 + j * 8);
            asm volatile("st.shared.v2.b32 [%0], {%1,%2};"
                         :: "r"(aAh + off), "r"(hp0), "r"(hp1) : "memory");
            asm volatile("st.shared.v2.b32 [%0], {%1,%2};"
                         :: "r"(aAl + off), "r"(lp0), "r"(lp1) : "memory");
        }
    };
    // fragment-reuse compute: a[] holds ah, fires 2 terms, then reloaded as al
    auto compute = [&](int p) {
        const uint32_t b = sb + (uint32_t)p * MMA_BUFB;
        const uint32_t aAh = b, aAl = b + 10240u;
        const uint32_t aBh = b + 20480u, aBl = b + 30720u;
        #pragma unroll
        for (int ks = 0; ks < 2; ks++) {
            uint32_t a[4][4], bh[4][2], bl[4][2];
            const int arl = lane & 15;
            const uint32_t ab = (uint32_t)((lane >> 4) * 16 + ks * 32);
            const int bn = (lane & 7) + ((lane >> 4) << 3);
            const uint32_t bb = (uint32_t)(((lane >> 3) & 1) * 16 + ks * 32);
            #pragma unroll
            for (int np = 0; np < 2; np++) {
                uint32_t off = (uint32_t)((wn + np * 16 + bn) * 80) + bb;
                uint32_t r0, r1, r2, r3;
                ldsm_x4(r0, r1, r2, r3, aBh + off);
                bh[np*2][0] = r0; bh[np*2][1] = r1;
                bh[np*2+1][0] = r2; bh[np*2+1][1] = r3;
                ldsm_x4(r0, r1, r2, r3, aBl + off);
                bl[np*2][0] = r0; bl[np*2][1] = r1;
                bl[np*2+1][0] = r2; bl[np*2+1][1] = r3;
            }
            #pragma unroll
            for (int mt = 0; mt < 4; mt++) {
                uint32_t off = (uint32_t)((wm + mt * 16 + arl) * 80) + ab;
                ldsm_x4(a[mt][0], a[mt][1], a[mt][2], a[mt][3], aAh + off);
            }
            #pragma unroll
            for (int mt = 0; mt < 4; mt++)
                #pragma unroll
                for (int nt = 0; nt < 4; nt++) {
                    mma_bf16(acc[mt][nt], a[mt], bh[nt]);
                    mma_bf16(acc[mt][nt], a[mt], bl[nt]);
                }
            #pragma unroll
            for (int mt = 0; mt < 4; mt++) {
                uint32_t off = (uint32_t)((wm + mt * 16 + arl) * 80) + ab;
                ldsm_x4(a[mt][0], a[mt][1], a[mt][2], a[mt][3], aAl + off);
            }
            #pragma unroll
            for (int mt = 0; mt < 4; mt++)
                #pragma unroll
                for (int nt = 0; nt < 4; nt++)
                    mma_bf16(acc[mt][nt], a[mt], bh[nt]);
        }
    };

    const int ntc = K >> 5;
    cpasyncB(0, 0);
    CP_COMMIT();
    loadG(0);
    storeS(0);
    CP_WAIT0();
    __syncthreads();
    #pragma unroll 1
    for (int ch = 0; ch < ntc - 1; ch++) {
        const int nxt = (ch + 1) & 1;
        cpasyncB((ch + 1) << 5, nxt);
        CP_COMMIT();
        loadG((ch + 1) << 5);
        compute(ch & 1);
        storeS(nxt);
        CP_WAIT0();
        __syncthreads();
    }
    compute((ntc - 1) & 1);

    #pragma unroll
    for (int nt = 0; nt < 4; nt++) {
        const int col = n0 + wn + nt * 8 + (lane & 3) * 2;
        const float2 bv = *reinterpret_cast<const float2*>(&bias[col]);
        #pragma unroll
        for (int mt = 0; mt < 4; mt++) {
            const int r0 = m0 + wm + mt * 16 + (lane >> 2);
            float u0 = acc[mt][nt][0] + bv.x;
            float u1 = acc[mt][nt][1] + bv.y;
            float u2 = acc[mt][nt][2] + bv.x;
            float u3 = acc[mt][nt][3] + bv.y;
            if (ACT == 1) {
                u0 = fmaxf(u0, 0.f); u1 = fmaxf(u1, 0.f);
                u2 = fmaxf(u2, 0.f); u3 = fmaxf(u3, 0.f);
            } else {
                u0 = tanhf(u0); u1 = tanhf(u1);
                u2 = tanhf(u2); u3 = tanhf(u3);
            }
            *reinterpret_cast<float2*>(&C[(size_t)r0 * N + col]) = make_float2(u0, u1);
            *reinterpret_cast<float2*>(&C[(size_t)(r0 + 8) * N + col]) = make_float2(u2, u3);
        }
    }
}

// ============================================================================
// weight split: W[K,N] f32 -> Wh/Wl [N,K] bf16 (transposed)
// ============================================================================
__global__ void wsplit_kernel(const float* __restrict__ W,
                              __nv_bfloat16* __restrict__ Wh,
                              __nv_bfloat16* __restrict__ Wl, int K, int N)
{
    int i = blockIdx.x * 256 + threadIdx.x;
    if (i >= K * N) return;
    int n = i / K, k = i - n * K;
    float w = W[(size_t)k * N + n];
    __nv_bfloat16 h = __float2bfloat16_rn(w);
    Wh[i] = h;
    Wl[i] = __float2bfloat16_rn(w - __bfloat162float(h));
}

// ============================================================================
// Scalar fp32 SGEMM, bitwise-exact sequential-k.
// MODE 0: normal. MODE 1: dense rows, count early-out. MODE 2: A rows via rlist.
// ============================================================================
template<int BM,int BN,int BK,int TM,int TN,int ACT,int MODE>
__global__ __launch_bounds__((BM/TM)*(BN/TN), 2)
void gemm_bias_act(const float* __restrict__ A, const float* __restrict__ B,
                   const float* __restrict__ bias, float* __restrict__ C,
                   int M, int N, int K,
                   const int* __restrict__ rows, const int* __restrict__ cntp)
{
    constexpr int NT = (BM/TM)*(BN/TN);
    constexpr int LA = (BM*BK)/(NT*4);
    constexpr int LB = (BK*BN)/(NT*4);

    __shared__ __align__(16) float As[2][BK][BM];
    __shared__ __align__(16) float Bs[2][BK][BN];
    __shared__ int srow[BM];

    const int tid = threadIdx.x;
    const int m0 = blockIdx.y * BM;
    const int n0 = blockIdx.x * BN;
    const int tx = tid % (BN/TN);
    const int ty = tid / (BN/TN);

    if (MODE >= 1) {
        const int cn = *cntp;
        if (cn == 0 || m0 >= cn) return;
        if (MODE == 2) {
            if (tid < BM) {
                int r = m0 + tid;
                srow[tid] = rows[r < cn ? r : (cn - 1)];
            }
            __syncthreads();
        }
    }

    float acc[TM][TN];
    #pragma unroll
    for (int i = 0; i < TM; i++)
        #pragma unroll
        for (int j = 0; j < TN; j++) acc[i][j] = 0.f;

    float4 ra[LA], rb[LB];

    #pragma unroll
    for (int j = 0; j < LA; j++) {
        int i = (tid + j*NT) * 4;
        int r = i / BK, c = i % BK;
        const int ar = (MODE == 2) ? srow[r] : (m0 + r);
        ra[j] = *reinterpret_cast<const float4*>(&A[(size_t)ar*K + c]);
    }
    #pragma unroll
    for (int j = 0; j < LB; j++) {
        int i = (tid + j*NT) * 4;
        int r = i / BN, c = i % BN;
        rb[j] = *reinterpret_cast<const float4*>(&B[(size_t)r*N + n0 + c]);
    }
    #pragma unroll
    for (int j = 0; j < LA; j++) {
        int i = (tid + j*NT) * 4;
        int r = i / BK, c = i % BK;
        As[0][c+0][r] = ra[j].x; As[0][c+1][r] = ra[j].y;
        As[0][c+2][r] = ra[j].z; As[0][c+3][r] = ra[j].w;
    }
    #pragma unroll
    for (int j = 0; j < LB; j++) {
        int i = (tid + j*NT) * 4;
        int r = i / BN, c = i % BN;
        *reinterpret_cast<float4*>(&Bs[0][r][c]) = rb[j];
    }
    __syncthreads();

    const int ntiles = K / BK;
    #pragma unroll 1
    for (int t = 1; t < ntiles; t++) {
        const int k0 = t * BK;
        #pragma unroll
        for (int j = 0; j < LA; j++) {
            int i = (tid + j*NT) * 4;
            int r = i / BK, c = i % BK;
            const int ar = (MODE == 2) ? srow[r] : (m0 + r);
            ra[j] = *reinterpret_cast<const float4*>(&A[(size_t)ar*K + k0 + c]);
        }
        #pragma unroll
        for (int j = 0; j < LB; j++) {
            int i = (tid + j*NT) * 4;
            int r = i / BN, c = i % BN;
            rb[j] = *reinterpret_cast<const float4*>(&B[(size_t)(k0 + r)*N + n0 + c]);
        }
        const int cur = (t - 1) & 1;
        #pragma unroll
        for (int k = 0; k < BK; k++) {
            float a[TM], b[TN];
            #pragma unroll
            for (int i = 0; i < TM; i += 4) {
                float4 v = *reinterpret_cast<const float4*>(&As[cur][k][ty*TM + i]);
                a[i] = v.x; a[i+1] = v.y; a[i+2] = v.z; a[i+3] = v.w;
            }
            #pragma unroll
            for (int j = 0; j < TN; j += 4) {
                float4 v = *reinterpret_cast<const float4*>(&Bs[cur][k][tx*TN + j]);
                b[j] = v.x; b[j+1] = v.y; b[j+2] = v.z; b[j+3] = v.w;
            }
            #pragma unroll
            for (int i = 0; i < TM; i++)
                #pragma unroll
                for (int j = 0; j < TN; j++)
                    acc[i][j] = fmaf(a[i], b[j], acc[i][j]);
        }
        const int nxt = t & 1;
        #pragma unroll
        for (int j = 0; j < LA; j++) {
            int i = (tid + j*NT) * 4;
            int r = i / BK, c = i % BK;
            As[nxt][c+0][r] = ra[j].x; As[nxt][c+1][r] = ra[j].y;
            As[nxt][c+2][r] = ra[j].z; As[nxt][c+3][r] = ra[j].w;
        }
        #pragma unroll
        for (int j = 0; j < LB; j++) {
            int i = (tid + j*NT) * 4;
            int r = i / BN, c = i % BN;
            *reinterpret_cast<float4*>(&Bs[nxt][r][c]) = rb[j];
        }
        __syncthreads();
    }
    {
        const int cur = (ntiles - 1) & 1;
        #pragma unroll
        for (int k = 0; k < BK; k++) {
            float a[TM], b[TN];
            #pragma unroll
            for (int i = 0; i < TM; i += 4) {
                float4 v = *reinterpret_cast<const float4*>(&As[cur][k][ty*TM + i]);
                a[i] = v.x; a[i+1] = v.y; a[i+2] = v.z; a[i+3] = v.w;
            }
            #pragma unroll
            for (int j = 0; j < TN; j += 4) {
                float4 v = *reinterpret_cast<const float4*>(&Bs[cur][k][tx*TN + j]);
                b[j] = v.x; b[j+1] = v.y; b[j+2] = v.z; b[j+3] = v.w;
            }
            #pragma unroll
            for (int i = 0; i < TM; i++)
                #pragma unroll
                for (int j = 0; j < TN; j++)
                    acc[i][j] = fmaf(a[i], b[j], acc[i][j]);
        }
    }

    float bv[TN];
    #pragma unroll
    for (int j = 0; j < TN; j++) bv[j] = bias[n0 + tx*TN + j];
    #pragma unroll
    for (int i = 0; i < TM; i++) {
        const int row = m0 + ty*TM + i;
        float* Cp = &C[(size_t)row*N + n0 + tx*TN];
        #pragma unroll
        for (int j = 0; j < TN; j += 4) {
            float vv[4];
            #pragma unroll
            for (int q = 0; q < 4; q++) {
                float u = acc[i][j+q] + bv[j+q];
                if (ACT == 1) u = fmaxf(u, 0.f);
                else if (ACT == 2) u = tanhf(u);
                vv[q] = u;
            }
            *reinterpret_cast<float4*>(&Cp[j]) = make_float4(vv[0], vv[1], vv[2], vv[3]);
        }
    }
}

// ============================================================================
// prep: codebook squared norms + zero loss + zero repair count
// ============================================================================
__global__ void prep_kernel(const float* __restrict__ cb)
{
    const int c = blockIdx.x * blockDim.x + threadIdx.x;
    if (c == 0) { g_loss = 0.0; g_rcnt = 0; }
    if (c < NCODE) {
        const float* p = &cb[(size_t)c * LATD];
        float s = 0.f;
        #pragma unroll
        for (int i = 0; i < LATD; i++) s = fmaf(p[i], p[i], s);
        g_esq[c] = s;
    }
}

// ============================================================================
// Approx VQ: reference-rounding dists on approx z; top-2 tracked; ambiguous
// rows (gap < TAU) -> repair list. Writes int idx, float idx, loss.
// ============================================================================
__global__ __launch_bounds__(256)
void vq_approx_kernel(const float* __restrict__ z, const float* __restrict__ cb,
                      int* __restrict__ idx_i, float* __restrict__ idx_out)
{
    __shared__ __align__(16) float4 sc[128 * 16];
    __shared__ float sesq[128];
    __shared__ float wsum[8];

    const int tid = threadIdx.x;
    const int row = blockIdx.x * 256 + tid;

    float4 zr[16];
    const float4* zp = reinterpret_cast<const float4*>(&z[(size_t)row * LATD]);
    #pragma unroll
    for (int i = 0; i < 16; i++) zr[i] = zp[i];

    float z_sq = 0.f;
    #pragma unroll
    for (int i = 0; i < 16; i++) {
        z_sq = fmaf(zr[i].x, zr[i].x, z_sq);
        z_sq = fmaf(zr[i].y, zr[i].y, z_sq);
        z_sq = fmaf(zr[i].z, zr[i].z, z_sq);
        z_sq = fmaf(zr[i].w, zr[i].w, z_sq);
    }

    float best = 3.4028235e38f, second = 3.4028235e38f;
    int bi = 0;
    for (int c0 = 0; c0 < NCODE; c0 += 128) {
        __syncthreads();
        const float4* cp = reinterpret_cast<const float4*>(&cb[(size_t)c0 * LATD]);
        #pragma unroll
        for (int j = 0; j < 8; j++) sc[tid + j*256] = cp[tid + j*256];
        if (tid < 128) sesq[tid] = g_esq[c0 + tid];
        __syncthreads();

        #pragma unroll 4
        for (int c = 0; c < 128; c++) {
            const float4* e = &sc[c * 16];
            float acc = 0.f;
            #pragma unroll
            for (int i = 0; i < 16; i++) {
                float4 v = e[i];
                acc = fmaf(zr[i].x, v.x, acc);
                acc = fmaf(zr[i].y, v.y, acc);
                acc = fmaf(zr[i].z, v.z, acc);
                acc = fmaf(zr[i].w, v.w, acc);
            }
            float t = z_sq - 2.0f * acc;
            float d = t + sesq[c];
            if (d < best) { second = best; best = d; bi = c0 + c; }
            else if (d < second) { second = d; }
        }
    }

    if (second - best < TAU) {
        int p = atomicAdd(&g_rcnt, 1);
        g_rlist[p] = row;
    }

    const float4* ep = reinterpret_cast<const float4*>(&cb[(size_t)bi * LATD]);
    float ls = 0.f;
    #pragma unroll
    for (int i = 0; i < 16; i++) {
        float4 e = ep[i];
        float dx = e.x - zr[i].x, dy = e.y - zr[i].y;
        float dz = e.z - zr[i].z, dw = e.w - zr[i].w;
        ls += dx*dx + dy*dy + dz*dz + dw*dw;
    }
    idx_i[row] = bi;
    idx_out[row] = (float)bi;

    #pragma unroll
    for (int o = 16; o > 0; o >>= 1) ls += __shfl_down_sync(0xffffffffu, ls, o);
    if ((tid & 31) == 0) wsum[tid >> 5] = ls;
    __syncthreads();
    if (tid == 0) {
        float s = 0.f;
        #pragma unroll
        for (int i = 0; i < 8; i++) s += wsum[i];
        atomicAdd(&g_loss, (double)s);
    }
}

// ============================================================================
// Repair VQ: exact argmin on exact z (dense zg rows), scatter idx.
// ============================================================================
__global__ __launch_bounds__(256)
void vq_repair_kernel(const float* __restrict__ zg, const float* __restrict__ cb,
                      int* __restrict__ idx_i, float* __restrict__ idx_out)
{
    __shared__ __align__(16) float4 sc[128 * 16];
    __shared__ float sesq[128];

    const int cn = g_rcnt;
    const int m0 = blockIdx.x * 256;
    if (cn == 0 || m0 >= cn) return;

    const int tid = threadIdx.x;
    int r = m0 + tid;
    if (r >= cn) r = cn - 1;

    float4 zr[16];
    const float4* zp = reinterpret_cast<const float4*>(&zg[(size_t)r * LATD]);
    #pragma unroll
    for (int i = 0; i < 16; i++) zr[i] = zp[i];

    float z_sq = 0.f;
    #pragma unroll
    for (int i = 0; i < 16; i++) {
        z_sq = fmaf(zr[i].x, zr[i].x, z_sq);
        z_sq = fmaf(zr[i].y, zr[i].y, z_sq);
        z_sq = fmaf(zr[i].z, zr[i].z, z_sq);
        z_sq = fmaf(zr[i].w, zr[i].w, z_sq);
    }

    float best = 3.4028235e38f;
    int bi = 0;
    for (int c0 = 0; c0 < NCODE; c0 += 128) {
        __syncthreads();
        const float4* cp = reinterpret_cast<const float4*>(&cb[(size_t)c0 * LATD]);
        #pragma unroll
        for (int j = 0; j < 8; j++) sc[tid + j*256] = cp[tid + j*256];
        if (tid < 128) sesq[tid] = g_esq[c0 + tid];
        __syncthreads();

        #pragma unroll 4
        for (int c = 0; c < 128; c++) {
            const float4* e = &sc[c * 16];
            float acc = 0.f;
            #pragma unroll
            for (int i = 0; i < 16; i++) {
                float4 v = e[i];
                acc = fmaf(zr[i].x, v.x, acc);
                acc = fmaf(zr[i].y, v.y, acc);
                acc = fmaf(zr[i].z, v.z, acc);
                acc = fmaf(zr[i].w, v.w, acc);
            }
            float t = z_sq - 2.0f * acc;
            float d = t + sesq[c];
            if (d < best) { best = d; bi = c0 + c; }
        }
    }

    const int orow = g_rlist[r];
    idx_i[orow] = bi;
    idx_out[orow] = (float)bi;
}

// ============================================================================
// gather: x_recon[row] = t3[idx[row]]  (4MB table, L2-resident; coalesced out)
// ============================================================================
__global__ __launch_bounds__(256)
void gather_kernel(const float* __restrict__ table, const int* __restrict__ idx,
                   float* __restrict__ outp)
{
    const int row  = blockIdx.x * 8 + (threadIdx.x >> 5);
    const int lane = threadIdx.x & 31;
    const float4* src = reinterpret_cast<const float4*>(
        &table[(size_t)idx[row] * IN_DIM]);
    float4* dst = reinterpret_cast<float4*>(&outp[(size_t)row * IN_DIM]);
    #pragma unroll
    for (int j = 0; j < 8; j++) dst[lane + 32*j] = src[lane + 32*j];
}

__global__ void fin_kernel(float* __restrict__ loss_out)
{
    loss_out[0] = (float)(COMMIT_BETA * g_loss / ((double)NROWS * LATD));
}

// ============================================================================
// launch  (mma_e1 at launch index 3 for ncu capture)
// ============================================================================
extern "C" void kernel_launch(void* const* d_in, const int* in_sizes, int n_in,
                              void* d_out, int out_size)
{
    const float* x   = (const float*)d_in[0];
    const float* We1 = (const float*)d_in[1];
    const float* be1 = (const float*)d_in[2];
    const float* We2 = (const float*)d_in[3];
    const float* be2 = (const float*)d_in[4];
    const float* We3 = (const float*)d_in[5];
    const float* be3 = (const float*)d_in[6];
    const float* cb  = (const float*)d_in[7];
    const float* Wd1 = (const float*)d_in[8];
    const float* bd1 = (const float*)d_in[9];
    const float* Wd2 = (const float*)d_in[10];
    const float* bd2 = (const float*)d_in[11];
    const float* Wd3 = (const float*)d_in[12];
    const float* bd3 = (const float*)d_in[13];

    float* out   = (float*)d_out;
    float* xrec  = out;
    float* zout  = out + (size_t)NROWS * IN_DIM;
    float* idxo  = zout + (size_t)NROWS * LATD;
    float* losso = idxo + NROWS;

    float *h1, *h2, *zg, *t1, *t2, *t3;
    int *idxi, *rlist, *rcnt;
    cudaGetSymbolAddress((void**)&h1, g_h1);
    cudaGetSymbolAddress((void**)&h2, g_h2);
    cudaGetSymbolAddress((void**)&zg, g_zg);
    cudaGetSymbolAddress((void**)&t1, g_t1);
    cudaGetSymbolAddress((void**)&t2, g_t2);
    cudaGetSymbolAddress((void**)&t3, g_t3);
    cudaGetSymbolAddress((void**)&idxi, g_idx);
    cudaGetSymbolAddress((void**)&rlist, g_rlist);
    cudaGetSymbolAddress((void**)&rcnt, g_rcnt);
    __nv_bfloat16 *e1h, *e1l, *e2h, *e2l;
    cudaGetSymbolAddress((void**)&e1h, g_e1h);
    cudaGetSymbolAddress((void**)&e1l, g_e1l);
    cudaGetSymbolAddress((void**)&e2h, g_e2h);
    cudaGetSymbolAddress((void**)&e2l, g_e2l);

    cudaFuncSetAttribute(mma_gemm<1>, cudaFuncAttributeMaxDynamicSharedMemorySize, MMA_DSM);

    // 0-2: prep + encoder weight splits
    prep_kernel<<<4, 256>>>(cb);
    wsplit_kernel<<<(IN_DIM*H1D + 255)/256, 256>>>(We1, e1h, e1l, IN_DIM, H1D);
    wsplit_kernel<<<(H1D*H2D  + 255)/256, 256>>>(We2, e2h, e2l, H1D, H2D);

    // 3: e1 on tensor cores (profiling target)
    mma_gemm<1><<<dim3(H1D/128, NROWS/128), 256, MMA_DSM>>>(x, e1h, e1l, be1, h1, IN_DIM, H1D);

    // decoder lookup tables (exact fp32; BN=64 for more CTAs on tiny grids)
    gemm_bias_act<128,64,16,8,4,1,0><<<dim3(H2D/64, NCODE/128), 256>>>(
        cb, Wd1, bd1, t1, NCODE, H2D, LATD, nullptr, nullptr);
    gemm_bias_act<128,64,16,8,4,1,0><<<dim3(H1D/64, NCODE/128), 256>>>(
        t1, Wd2, bd2, t2, NCODE, H1D, H2D, nullptr, nullptr);
    gemm_bias_act<128,64,16,8,4,2,0><<<dim3(IN_DIM/64, NCODE/128), 256>>>(
        t2, Wd3, bd3, t3, NCODE, IN_DIM, H1D, nullptr, nullptr);

    // rest of approx encoder
    mma_gemm<1><<<dim3(H2D/128, NROWS/128), 256, MMA_DSM>>>(h1, e2h, e2l, be2, h2, H1D, H2D);
    gemm_bias_act<128,64,16,8,4,0,0><<<dim3(1, NROWS/128), 256>>>(
        h2, We3, be3, zout, NROWS, LATD, H2D, nullptr, nullptr);

    // approx VQ + ambiguity detection
    vq_approx_kernel<<<NROWS/256, 256>>>(zout, cb, idxi, idxo);

    // exact repair chain (bitwise fp32, only listed rows do real work)
    gemm_bias_act<128,128,16,8,8,1,2><<<dim3(H1D/128, NROWS/128), 256>>>(
        x,  We1, be1, h1, NROWS, H1D, IN_DIM, rlist, rcnt);
    gemm_bias_act<128,128,16,8,8,1,1><<<dim3(H2D/128, NROWS/128), 256>>>(
        h1, We2, be2, h2, NROWS, H2D, H1D, nullptr, rcnt);
    gemm_bias_act<128,64,16,8,4,0,1><<<dim3(1, NROWS/128), 256>>>(
        h2, We3, be3, zg, NROWS, LATD, H2D, nullptr, rcnt);
    vq_repair_kernel<<<NROWS/256, 256>>>(zg, cb, idxi, idxo);

    // x_recon = decoder-table gather on repaired indices
    gather_kernel<<<NROWS/8, 256>>>(t3, idxi, xrec);

    fin_kernel<<<1, 1>>>(losso);
}